// round 1
// baseline (speedup 1.0000x reference)
#include <cuda_runtime.h>
#include <cuda_bf16.h>

// Problem constants
#define BATCH 4
#define DIM   1024
#define HEADS 16
#define DK    64
#define NN    1024
#define LAYERS 4
#define TWOD  2048
#define BN_EPS 1e-5f

// ---------------------------------------------------------------------------
// Scratch (device globals — no allocation allowed)
// ---------------------------------------------------------------------------
__device__ float g_Q  [BATCH * DIM * NN];
__device__ float g_K  [BATCH * DIM * NN];
__device__ float g_V  [BATCH * DIM * NN];
__device__ float g_ATT[BATCH * DIM * NN];
__device__ float g_MRG[BATCH * DIM * NN];
__device__ float g_H1 [BATCH * TWOD * NN];
__device__ float g_X0 [BATCH * DIM * NN];
__device__ float g_X1 [BATCH * DIM * NN];
__device__ float g_S  [(long)BATCH * HEADS * NN * NN];   // 256 MB scores

// ---------------------------------------------------------------------------
// Generic fused GEMM: C[b,i,n0+j] = sum_k A[i,k] * X[b,k,j]  (+bias, BN+ReLU, +res)
// A row-major (M x K). X operand split in K: k < Ksplit -> X1, else X2.
// Columns j global over B*NN; each 64-col block lies inside one batch.
// BM=128, BN=64, BK=16, 256 threads, 8x4 per-thread microtile.
// ---------------------------------------------------------------------------
__global__ __launch_bounds__(256)
void gemm_k(const float* __restrict__ A, int lda,
            const float* __restrict__ X1, long xbs1,
            const float* __restrict__ X2, long xbs2, int Ksplit,
            const float* __restrict__ bias,
            const float* __restrict__ bng, const float* __restrict__ bnb,
            const float* __restrict__ bnm, const float* __restrict__ bnv,
            const float* __restrict__ res, long rbs,
            float* __restrict__ C, long cbs,
            int K)
{
    __shared__ float As[16][128];
    __shared__ float Bs[16][64];
    const int tid = threadIdx.x;
    const int tx = tid & 15, ty = tid >> 4;
    const int j0 = blockIdx.x * 64;
    const int b  = j0 >> 10;           // NN = 1024
    const int n0 = j0 & 1023;
    const int i0 = blockIdx.y * 128;

    const float* x1b = X1 + (long)b * xbs1;
    const float* x2b = X2 ? (X2 + (long)b * xbs2) : X1;

    float acc[2][4][4];
#pragma unroll
    for (int h = 0; h < 2; h++)
#pragma unroll
        for (int ii = 0; ii < 4; ii++)
#pragma unroll
            for (int jj = 0; jj < 4; jj++) acc[h][ii][jj] = 0.f;

    const int arow = tid >> 1;          // 0..127
    const int acol = (tid & 1) * 8;     // 0 or 8
    const int brow = tid >> 4;          // 0..15
    const int bcol = (tid & 15) * 4;    // 0..60

    for (int k0 = 0; k0 < K; k0 += 16) {
        const float* ap = A + (long)(i0 + arow) * lda + (k0 + acol);
        float4 a0 = *(const float4*)ap;
        float4 a1 = *(const float4*)(ap + 4);
        As[acol + 0][arow] = a0.x; As[acol + 1][arow] = a0.y;
        As[acol + 2][arow] = a0.z; As[acol + 3][arow] = a0.w;
        As[acol + 4][arow] = a1.x; As[acol + 5][arow] = a1.y;
        As[acol + 6][arow] = a1.z; As[acol + 7][arow] = a1.w;
        const int kg = k0 + brow;
        const float* rp = (kg < Ksplit) ? (x1b + (long)kg * NN)
                                        : (x2b + (long)(kg - Ksplit) * NN);
        *(float4*)&Bs[brow][bcol] = *(const float4*)(rp + n0 + bcol);
        __syncthreads();
#pragma unroll
        for (int kk = 0; kk < 16; kk++) {
            float4 alo = *(const float4*)&As[kk][ty * 4];
            float4 ahi = *(const float4*)&As[kk][ty * 4 + 64];
            float4 bv  = *(const float4*)&Bs[kk][tx * 4];
            float av[2][4] = {{alo.x, alo.y, alo.z, alo.w},
                              {ahi.x, ahi.y, ahi.z, ahi.w}};
            float bb[4] = {bv.x, bv.y, bv.z, bv.w};
#pragma unroll
            for (int h = 0; h < 2; h++)
#pragma unroll
                for (int ii = 0; ii < 4; ii++)
#pragma unroll
                    for (int jj = 0; jj < 4; jj++)
                        acc[h][ii][jj] = fmaf(av[h][ii], bb[jj], acc[h][ii][jj]);
        }
        __syncthreads();
    }

    float* cb = C + (long)b * cbs;
    const float* rb = res ? res + (long)b * rbs : nullptr;
#pragma unroll
    for (int h = 0; h < 2; h++) {
#pragma unroll
        for (int ii = 0; ii < 4; ii++) {
            const int i = i0 + h * 64 + ty * 4 + ii;
            const float bi = bias[i];
            float sa = 0.f, sb = 0.f;
            if (bng) {
                const float inv = rsqrtf(bnv[i] + BN_EPS);
                sa = bng[i] * inv;
                sb = bnb[i] - sa * bnm[i];
            }
            float out[4];
#pragma unroll
            for (int jj = 0; jj < 4; jj++) {
                float v = acc[h][ii][jj] + bi;
                if (bng) { v = fmaf(sa, v, sb); v = fmaxf(v, 0.f); }
                out[jj] = v;
            }
            const int j = n0 + tx * 4;
            if (rb) {
                float4 r = *(const float4*)(rb + (long)i * NN + j);
                out[0] += r.x; out[1] += r.y; out[2] += r.z; out[3] += r.w;
            }
            *(float4*)(cb + (long)i * NN + j) =
                make_float4(out[0], out[1], out[2], out[3]);
        }
    }
}

// ---------------------------------------------------------------------------
// scores[bh, n, m] = (1/8) * sum_dk Q[b, dk*H+h, n] * K[b, dk*H+h, m]
// Tiles: 64 n x 64 m, DK=64 entirely in smem. grid (N/64, N/64, B*H)
// ---------------------------------------------------------------------------
__global__ __launch_bounds__(256)
void scores_k(const float* __restrict__ Q, const float* __restrict__ Kk,
              float* __restrict__ S)
{
    __shared__ float Qs[64][64];
    __shared__ float Ks[64][64];
    const int tid = threadIdx.x;
    const int tx = tid & 15, ty = tid >> 4;
    const int n0 = blockIdx.x * 64;
    const int m0 = blockIdx.y * 64;
    const int bh = blockIdx.z;
    const int b = bh >> 4, h = bh & 15;
    const float* qb = Q + (long)b * (DIM * NN) + h * NN;
    const float* kb = Kk + (long)b * (DIM * NN) + h * NN;

    const int dkr = tid >> 4, col = (tid & 15) * 4;
#pragma unroll
    for (int r = 0; r < 4; r++) {
        const int dk = dkr + 16 * r;                // channel stride = H*NN
        *(float4*)&Qs[dk][col] = *(const float4*)(qb + (long)dk * (HEADS * NN) + n0 + col);
        *(float4*)&Ks[dk][col] = *(const float4*)(kb + (long)dk * (HEADS * NN) + m0 + col);
    }
    __syncthreads();

    float acc[4][4];
#pragma unroll
    for (int ii = 0; ii < 4; ii++)
#pragma unroll
        for (int jj = 0; jj < 4; jj++) acc[ii][jj] = 0.f;

#pragma unroll 8
    for (int dk = 0; dk < 64; dk++) {
        float4 a  = *(const float4*)&Qs[dk][ty * 4];
        float4 bv = *(const float4*)&Ks[dk][tx * 4];
        float av[4] = {a.x, a.y, a.z, a.w};
        float bb[4] = {bv.x, bv.y, bv.z, bv.w};
#pragma unroll
        for (int ii = 0; ii < 4; ii++)
#pragma unroll
            for (int jj = 0; jj < 4; jj++)
                acc[ii][jj] = fmaf(av[ii], bb[jj], acc[ii][jj]);
    }

    float* sb = S + (long)bh * NN * NN;
    const float sc = 0.125f;  // 1/sqrt(64)
#pragma unroll
    for (int ii = 0; ii < 4; ii++) {
        const int n = n0 + ty * 4 + ii;
        *(float4*)(sb + (long)n * NN + m0 + tx * 4) =
            make_float4(acc[ii][0] * sc, acc[ii][1] * sc,
                        acc[ii][2] * sc, acc[ii][3] * sc);
    }
}

// ---------------------------------------------------------------------------
// Row softmax in place over the last dim (1024). One block per row.
// ---------------------------------------------------------------------------
__global__ __launch_bounds__(256)
void softmax_k(float* __restrict__ S)
{
    float* p = S + (long)blockIdx.x * NN;
    const int tid = threadIdx.x;
    float4 v = *(float4*)(p + tid * 4);

    float m = fmaxf(fmaxf(v.x, v.y), fmaxf(v.z, v.w));
#pragma unroll
    for (int o = 16; o; o >>= 1) m = fmaxf(m, __shfl_xor_sync(0xffffffffu, m, o));
    __shared__ float red[8];
    const int wid = tid >> 5, lid = tid & 31;
    if (lid == 0) red[wid] = m;
    __syncthreads();
    float mm = red[0];
#pragma unroll
    for (int i = 1; i < 8; i++) mm = fmaxf(mm, red[i]);
    __syncthreads();

    v.x = __expf(v.x - mm); v.y = __expf(v.y - mm);
    v.z = __expf(v.z - mm); v.w = __expf(v.w - mm);
    float s = v.x + v.y + v.z + v.w;
#pragma unroll
    for (int o = 16; o; o >>= 1) s += __shfl_xor_sync(0xffffffffu, s, o);
    if (lid == 0) red[wid] = s;
    __syncthreads();
    float tot = red[0];
#pragma unroll
    for (int i = 1; i < 8; i++) tot += red[i];
    const float inv = 1.f / tot;
    v.x *= inv; v.y *= inv; v.z *= inv; v.w *= inv;
    *(float4*)(p + tid * 4) = v;
}

// ---------------------------------------------------------------------------
// attn[b, dk*H+h, n] = sum_m W[bh, n, m] * V[b, dk*H+h, m]
// Output tile 64(dk) x 64(n), contraction over m in 64-tiles. grid (N/64, B*H)
// ---------------------------------------------------------------------------
__global__ __launch_bounds__(256)
void attnout_k(const float* __restrict__ W, const float* __restrict__ V,
               float* __restrict__ O)
{
    __shared__ float Vs[64][68];    // [dk][m], +4 pad
    __shared__ float Ws[64][68];    // [n ][m]
    const int tid = threadIdx.x;
    const int tx = tid & 15, ty = tid >> 4;
    const int n0 = blockIdx.x * 64;
    const int bh = blockIdx.y;
    const int b = bh >> 4, h = bh & 15;
    const float* vb = V + (long)b * (DIM * NN) + h * NN;
    const float* wb = W + (long)bh * NN * NN;

    float acc[4][4];
#pragma unroll
    for (int ii = 0; ii < 4; ii++)
#pragma unroll
        for (int jj = 0; jj < 4; jj++) acc[ii][jj] = 0.f;

    const int rr = tid >> 4, col = (tid & 15) * 4;
    for (int m0 = 0; m0 < NN; m0 += 64) {
#pragma unroll
        for (int r = 0; r < 4; r++) {
            const int q = rr + 16 * r;
            *(float4*)&Vs[q][col] = *(const float4*)(vb + (long)q * (HEADS * NN) + m0 + col);
            *(float4*)&Ws[q][col] = *(const float4*)(wb + (long)(n0 + q) * NN + m0 + col);
        }
        __syncthreads();
#pragma unroll 8
        for (int mm = 0; mm < 64; mm++) {
            float av[4], bv[4];
#pragma unroll
            for (int ii = 0; ii < 4; ii++) av[ii] = Vs[ty * 4 + ii][mm];
#pragma unroll
            for (int jj = 0; jj < 4; jj++) bv[jj] = Ws[tx * 4 + jj][mm];
#pragma unroll
            for (int ii = 0; ii < 4; ii++)
#pragma unroll
                for (int jj = 0; jj < 4; jj++)
                    acc[ii][jj] = fmaf(av[ii], bv[jj], acc[ii][jj]);
        }
        __syncthreads();
    }

    float* ob = O + (long)b * (DIM * NN) + h * NN;
#pragma unroll
    for (int ii = 0; ii < 4; ii++) {
        const int dk = ty * 4 + ii;
        *(float4*)(ob + (long)dk * (HEADS * NN) + n0 + tx * 4) =
            make_float4(acc[ii][0], acc[ii][1], acc[ii][2], acc[ii][3]);
    }
}

// ---------------------------------------------------------------------------
// Host launch
// ---------------------------------------------------------------------------
extern "C" void kernel_launch(void* const* d_in, const int* in_sizes, int n_in,
                              void* d_out, int out_size)
{
    const float* motion = (const float*)d_in[0];
    const float* Wq = (const float*)d_in[1];
    const float* bq = (const float*)d_in[2];
    const float* Wk = (const float*)d_in[3];
    const float* bk = (const float*)d_in[4];
    const float* Wv = (const float*)d_in[5];
    const float* bv = (const float*)d_in[6];
    const float* Wm = (const float*)d_in[7];
    const float* bm = (const float*)d_in[8];
    const float* Wp1 = (const float*)d_in[9];
    const float* bp1 = (const float*)d_in[10];
    const float* bng = (const float*)d_in[11];
    const float* bnb = (const float*)d_in[12];
    const float* bnm = (const float*)d_in[13];
    const float* bnv = (const float*)d_in[14];
    const float* Wp2 = (const float*)d_in[15];
    const float* bp2 = (const float*)d_in[16];
    float* out = (float*)d_out;

    float *Qb, *Kb, *Vb, *ATT, *MRG, *H1, *X0, *X1, *S;
    cudaGetSymbolAddress((void**)&Qb,  g_Q);
    cudaGetSymbolAddress((void**)&Kb,  g_K);
    cudaGetSymbolAddress((void**)&Vb,  g_V);
    cudaGetSymbolAddress((void**)&ATT, g_ATT);
    cudaGetSymbolAddress((void**)&MRG, g_MRG);
    cudaGetSymbolAddress((void**)&H1,  g_H1);
    cudaGetSymbolAddress((void**)&X0,  g_X0);
    cudaGetSymbolAddress((void**)&X1,  g_X1);
    cudaGetSymbolAddress((void**)&S,   g_S);

    const long BDN = (long)DIM * NN;        // per-batch stride for D x N tensors
    const long B2DN = (long)TWOD * NN;

    const dim3 gProj(64, DIM / 128);        // M=1024
    const dim3 gP1(64, TWOD / 128);         // M=2048
    const dim3 gScores(NN / 64, NN / 64, BATCH * HEADS);
    const dim3 gAttn(NN / 64, BATCH * HEADS);

    for (int l = 0; l < LAYERS; l++) {
        const float* xin = (l == 0) ? motion : ((l & 1) ? X1 : X0);
        float* xout = (l == 3) ? out : ((l & 1) ? X0 : X1);

        const float* Wql = Wq + (long)l * DIM * DIM;
        const float* Wkl = Wk + (long)l * DIM * DIM;
        const float* Wvl = Wv + (long)l * DIM * DIM;
        const float* Wml = Wm + (long)l * DIM * DIM;
        const float* Wp1l = Wp1 + (long)l * TWOD * TWOD;
        const float* Wp2l = Wp2 + (long)l * DIM * TWOD;

        // Q, K, V projections
        gemm_k<<<gProj, 256>>>(Wql, DIM, xin, BDN, nullptr, 0, DIM,
                               bq + l * DIM, nullptr, nullptr, nullptr, nullptr,
                               nullptr, 0, Qb, BDN, DIM);
        gemm_k<<<gProj, 256>>>(Wkl, DIM, xin, BDN, nullptr, 0, DIM,
                               bk + l * DIM, nullptr, nullptr, nullptr, nullptr,
                               nullptr, 0, Kb, BDN, DIM);
        gemm_k<<<gProj, 256>>>(Wvl, DIM, xin, BDN, nullptr, 0, DIM,
                               bv + l * DIM, nullptr, nullptr, nullptr, nullptr,
                               nullptr, 0, Vb, BDN, DIM);

        // Attention
        scores_k<<<gScores, 256>>>(Qb, Kb, S);
        softmax_k<<<BATCH * HEADS * NN, 256>>>(S);
        attnout_k<<<gAttn, 256>>>(S, Vb, ATT);

        // merge projection
        gemm_k<<<gProj, 256>>>(Wml, DIM, ATT, BDN, nullptr, 0, DIM,
                               bm + l * DIM, nullptr, nullptr, nullptr, nullptr,
                               nullptr, 0, MRG, BDN, DIM);

        // p1: Wp1 @ concat(merged, x) + bp1 -> BN -> ReLU
        gemm_k<<<gP1, 256>>>(Wp1l, TWOD, MRG, BDN, xin, BDN, DIM,
                             bp1 + l * TWOD,
                             bng + l * TWOD, bnb + l * TWOD,
                             bnm + l * TWOD, bnv + l * TWOD,
                             nullptr, 0, H1, B2DN, TWOD);

        // p2: Wp2 @ h + bp2 + x (residual)
        gemm_k<<<gProj, 256>>>(Wp2l, TWOD, H1, B2DN, nullptr, 0, TWOD,
                               bp2 + l * DIM, nullptr, nullptr, nullptr, nullptr,
                               xin, BDN, xout, BDN, TWOD);
    }
}

// round 5
// speedup vs baseline: 1.7877x; 1.7877x over previous
#include <cuda_runtime.h>
#include <cuda_bf16.h>
#include <cstdint>

#define BATCH 4
#define DIM   1024
#define HEADS 16
#define DK    64
#define NN    1024
#define LAYERS 4
#define TWOD  2048
#define BN_EPS 1e-5f

// ---------------------------------------------------------------------------
// Scratch (device globals — no allocation allowed)
// ---------------------------------------------------------------------------
__device__ float g_Q  [BATCH * DIM * NN];
__device__ float g_K  [BATCH * DIM * NN];
__device__ float g_V  [BATCH * DIM * NN];
__device__ float g_ATT[BATCH * DIM * NN];
__device__ float g_MRG[BATCH * DIM * NN];
__device__ float g_H1 [BATCH * TWOD * NN];
__device__ float g_X0 [BATCH * DIM * NN];
__device__ float g_X1 [BATCH * DIM * NN];
__device__ float g_S  [(long)BATCH * HEADS * NN * NN];   // 256 MB scores

// bf16 hi/lo weight copies (converted each call)
__device__ __nv_bfloat16 g_WqH[LAYERS * DIM * DIM],  g_WqL[LAYERS * DIM * DIM];
__device__ __nv_bfloat16 g_WkH[LAYERS * DIM * DIM],  g_WkL[LAYERS * DIM * DIM];
__device__ __nv_bfloat16 g_WvH[LAYERS * DIM * DIM],  g_WvL[LAYERS * DIM * DIM];
__device__ __nv_bfloat16 g_WmH[LAYERS * DIM * DIM],  g_WmL[LAYERS * DIM * DIM];
__device__ __nv_bfloat16 g_W1H[LAYERS * TWOD * TWOD], g_W1L[LAYERS * TWOD * TWOD];
__device__ __nv_bfloat16 g_W2H[LAYERS * DIM * TWOD],  g_W2L[LAYERS * DIM * TWOD];

// bf16 hi/lo transposed activations (per-layer reuse): [b][n][k]
__device__ __nv_bfloat16 g_XTh[BATCH * NN * DIM],  g_XTl[BATCH * NN * DIM];
__device__ __nv_bfloat16 g_ATh[BATCH * NN * DIM],  g_ATl[BATCH * NN * DIM];
__device__ __nv_bfloat16 g_MTh[BATCH * NN * DIM],  g_MTl[BATCH * NN * DIM];
__device__ __nv_bfloat16 g_HTh[BATCH * NN * TWOD], g_HTl[BATCH * NN * TWOD];

// ---------------------------------------------------------------------------
// PTX helpers (base sm_80+ ISA only — no tcgen05 on this build target)
// ---------------------------------------------------------------------------
__device__ __forceinline__ uint32_t smem_u32(const void* p) {
    return (uint32_t)__cvta_generic_to_shared(p);
}
__device__ __forceinline__ void cpa16(uint32_t dst, const void* src) {
    asm volatile("cp.async.cg.shared.global [%0], [%1], 16;"
                 :: "r"(dst), "l"(__cvta_generic_to_global(src)) : "memory");
}
#define CP_COMMIT() asm volatile("cp.async.commit_group;" ::: "memory")
#define CP_WAIT1()  asm volatile("cp.async.wait_group 1;" ::: "memory")
#define CP_WAIT0()  asm volatile("cp.async.wait_group 0;" ::: "memory")

__device__ __forceinline__ void ldm4(uint32_t& r0, uint32_t& r1, uint32_t& r2,
                                     uint32_t& r3, uint32_t addr) {
    asm volatile("ldmatrix.sync.aligned.m8n8.x4.shared.b16 {%0,%1,%2,%3}, [%4];"
                 : "=r"(r0), "=r"(r1), "=r"(r2), "=r"(r3) : "r"(addr));
}
__device__ __forceinline__ void mma_bf16(float& c0, float& c1, float& c2, float& c3,
                                         uint32_t a0, uint32_t a1, uint32_t a2,
                                         uint32_t a3, uint32_t b0, uint32_t b1) {
    asm volatile("mma.sync.aligned.m16n8k16.row.col.f32.bf16.bf16.f32 "
                 "{%0,%1,%2,%3}, {%4,%5,%6,%7}, {%8,%9}, {%0,%1,%2,%3};"
                 : "+f"(c0), "+f"(c1), "+f"(c2), "+f"(c3)
                 : "r"(a0), "r"(a1), "r"(a2), "r"(a3), "r"(b0), "r"(b1));
}

// ---------------------------------------------------------------------------
// Conversion: fp32 -> bf16 hi/lo split
// ---------------------------------------------------------------------------
__device__ __forceinline__ void split2(float x, __nv_bfloat16& h, __nv_bfloat16& l) {
    h = __float2bfloat16(x);
    l = __float2bfloat16(x - __bfloat162float(h));
}

__global__ __launch_bounds__(256)
void cvt_w(const float* __restrict__ w, __nv_bfloat16* __restrict__ hi,
           __nv_bfloat16* __restrict__ lo, int n)
{
    int i = (blockIdx.x * 256 + threadIdx.x) * 4;
    if (i >= n) return;
    float4 v = *(const float4*)(w + i);
    split2(v.x, hi[i + 0], lo[i + 0]);
    split2(v.y, hi[i + 1], lo[i + 1]);
    split2(v.z, hi[i + 2], lo[i + 2]);
    split2(v.w, hi[i + 3], lo[i + 3]);
}

// Transpose + convert: in [b][K][NN] fp32 -> out [b][NN][K] bf16 hi/lo
__global__ __launch_bounds__(256)
void tcvt(const float* __restrict__ in, __nv_bfloat16* __restrict__ hi,
          __nv_bfloat16* __restrict__ lo, int K)
{
    __shared__ float t[32][33];
    const int b = blockIdx.z;
    const float* ip = in + (long)b * K * NN;
    __nv_bfloat16* hp = hi + (long)b * NN * K;
    __nv_bfloat16* lp = lo + (long)b * NN * K;
    const int n0 = blockIdx.x * 32, k0 = blockIdx.y * 32;
    const int tx = threadIdx.x, ty = threadIdx.y;  // (32, 8)
#pragma unroll
    for (int r = 0; r < 4; r++) {
        int kk = ty + r * 8;
        t[kk][tx] = ip[(long)(k0 + kk) * NN + n0 + tx];
    }
    __syncthreads();
#pragma unroll
    for (int r = 0; r < 4; r++) {
        int nn = ty + r * 8;
        float v = t[tx][nn];
        long o = (long)(n0 + nn) * K + k0 + tx;
        split2(v, hp[o], lp[o]);
    }
}

// ---------------------------------------------------------------------------
// HMMA GEMM: C[b, i, n0+j] = sum_k A[i,k] * B[b,j,k]  (A row-major, B [n][k])
// bf16 hi/lo 3-pass split, fp32 accum. BM=128, BN=128, K-chunk 32,
// cp.async double buffer. B split in K at chunk nc1 (concat support).
// smem stage layout: Ah(8K) Al(8K) Bh(8K) Bl(8K); chunk16B swizzle ^((row>>1)&3)
// ---------------------------------------------------------------------------
#define MG_SMEM (2 * 32768)

__global__ __launch_bounds__(256, 1)
void mma_gemm(const __nv_bfloat16* __restrict__ Ah, const __nv_bfloat16* __restrict__ Al,
              int lda,
              const __nv_bfloat16* __restrict__ B1h, const __nv_bfloat16* __restrict__ B1l,
              int ldb1, int nc1,
              const __nv_bfloat16* __restrict__ B2h, const __nv_bfloat16* __restrict__ B2l,
              int ldb2, int nctot,
              const float* __restrict__ bias,
              const float* __restrict__ bng, const float* __restrict__ bnb,
              const float* __restrict__ bnm, const float* __restrict__ bnv,
              const float* __restrict__ res, float* __restrict__ C, long cbs)
{
    extern __shared__ __align__(128) char dsm[];
    const uint32_t smem_base = smem_u32(dsm);

    const int tid = threadIdx.x;
    const int wid = tid >> 5, lid = tid & 31;
    const int warp_m = wid & 1;          // 2 warps over M (64 rows each)
    const int warp_n = wid >> 1;         // 4 warps over N (32 cols each)
    const int j0 = blockIdx.x * 128;
    const int b  = j0 >> 10;
    const int n0 = j0 & 1023;
    const int i0 = blockIdx.y * 128;

    const __nv_bfloat16* b1h = B1h + (long)b * NN * ldb1;
    const __nv_bfloat16* b1l = B1l + (long)b * NN * ldb1;
    const __nv_bfloat16* b2h = B2h + (long)b * NN * ldb2;
    const __nv_bfloat16* b2l = B2l + (long)b * NN * ldb2;

    // ldmatrix fragment offsets (per lane): frow 0..15, fchk 0/1
    const int frow = ((lid >> 3) & 1) * 8 + (lid & 7);
    const int fchk = lid >> 4;
    uint32_t offA[4][2], offB[2][2];
#pragma unroll
    for (int mt = 0; mt < 4; mt++) {
        const int row = warp_m * 64 + mt * 16 + frow;
#pragma unroll
        for (int s16 = 0; s16 < 2; s16++) {
            const int ch = s16 * 2 + fchk;
            offA[mt][s16] = row * 64 + ((ch ^ ((row >> 1) & 3)) << 4);
        }
    }
#pragma unroll
    for (int np = 0; np < 2; np++) {
        const int row = warp_n * 32 + np * 16 + frow;
#pragma unroll
        for (int s16 = 0; s16 < 2; s16++) {
            const int ch = s16 * 2 + fchk;
            offB[np][s16] = row * 64 + ((ch ^ ((row >> 1) & 3)) << 4);
        }
    }

    float acc[4][4][4];
#pragma unroll
    for (int mt = 0; mt < 4; mt++)
#pragma unroll
        for (int nt = 0; nt < 4; nt++)
#pragma unroll
            for (int q = 0; q < 4; q++) acc[mt][nt][q] = 0.f;

    // stage loader: si = it*256 + tid -> row = si>>2 (0..127), ch = si&3
    auto load_stage = [&](int c, int s) {
        const uint32_t sb = smem_base + s * 32768;
        const __nv_bfloat16 *pbh, *pbl;
        long kb;
        int ldb;
        if (c < nc1) { pbh = b1h; pbl = b1l; ldb = ldb1; kb = (long)c * 32; }
        else         { pbh = b2h; pbl = b2l; ldb = ldb2; kb = (long)(c - nc1) * 32; }
#pragma unroll
        for (int it = 0; it < 2; it++) {
            const int si = it * 256 + tid;
            const int row = si >> 2, ch = si & 3;
            const uint32_t dsw = row * 64 + ((ch ^ ((row >> 1) & 3)) << 4);
            cpa16(sb + dsw,          Ah + (long)(i0 + row) * lda + (long)c * 32 + ch * 8);
            cpa16(sb + 8192 + dsw,   Al + (long)(i0 + row) * lda + (long)c * 32 + ch * 8);
            cpa16(sb + 16384 + dsw,  pbh + (long)(n0 + row) * ldb + kb + ch * 8);
            cpa16(sb + 24576 + dsw,  pbl + (long)(n0 + row) * ldb + kb + ch * 8);
        }
    };

    load_stage(0, 0);
    CP_COMMIT();

    for (int c = 0; c < nctot; c++) {
        if (c + 1 < nctot) {
            load_stage(c + 1, (c + 1) & 1);
            CP_COMMIT();
            CP_WAIT1();
        } else {
            CP_WAIT0();
        }
        __syncthreads();

        const uint32_t sb  = smem_base + (c & 1) * 32768;
        const uint32_t sAh = sb, sAl = sb + 8192, sBh = sb + 16384, sBl = sb + 24576;
#pragma unroll
        for (int s16 = 0; s16 < 2; s16++) {
            uint32_t ah[4][4], al_[4][4], bh[2][4], bl[2][4];
#pragma unroll
            for (int mt = 0; mt < 4; mt++) {
                ldm4(ah[mt][0], ah[mt][1], ah[mt][2], ah[mt][3], sAh + offA[mt][s16]);
                ldm4(al_[mt][0], al_[mt][1], al_[mt][2], al_[mt][3], sAl + offA[mt][s16]);
            }
#pragma unroll
            for (int np = 0; np < 2; np++) {
                ldm4(bh[np][0], bh[np][1], bh[np][2], bh[np][3], sBh + offB[np][s16]);
                ldm4(bl[np][0], bl[np][1], bl[np][2], bl[np][3], sBl + offB[np][s16]);
            }
#pragma unroll
            for (int mt = 0; mt < 4; mt++) {
#pragma unroll
                for (int nt = 0; nt < 4; nt++) {
                    const int np = nt >> 1, o = nt & 1;
                    float* a = acc[mt][nt];
                    mma_bf16(a[0], a[1], a[2], a[3],
                             ah[mt][0], ah[mt][1], ah[mt][2], ah[mt][3],
                             bh[np][o], bh[np][o + 2]);
                    mma_bf16(a[0], a[1], a[2], a[3],
                             ah[mt][0], ah[mt][1], ah[mt][2], ah[mt][3],
                             bl[np][o], bl[np][o + 2]);
                    mma_bf16(a[0], a[1], a[2], a[3],
                             al_[mt][0], al_[mt][1], al_[mt][2], al_[mt][3],
                             bh[np][o], bh[np][o + 2]);
                }
            }
        }
        __syncthreads();
    }

    // epilogue
    const int g = lid >> 2, t = lid & 3;
    const bool bn = (bng != nullptr);
#pragma unroll
    for (int mt = 0; mt < 4; mt++) {
#pragma unroll
        for (int half = 0; half < 2; half++) {
            const int r = i0 + warp_m * 64 + mt * 16 + g + half * 8;
            const float bi = bias[r];
            float sa = 0.f, sbb = 0.f;
            if (bn) {
                const float inv = rsqrtf(bnv[r] + BN_EPS);
                sa = bng[r] * inv;
                sbb = bnb[r] - sa * bnm[r];
            }
            float* cp_ = C + (long)b * cbs + (long)r * NN + n0 + warp_n * 32 + t * 2;
            const float* rp = res ? res + (long)b * ((long)DIM * NN) + (long)r * NN
                                        + n0 + warp_n * 32 + t * 2
                                  : nullptr;
#pragma unroll
            for (int nt = 0; nt < 4; nt++) {
                float v0 = acc[mt][nt][half * 2 + 0] + bi;
                float v1 = acc[mt][nt][half * 2 + 1] + bi;
                if (bn) {
                    v0 = fmaxf(fmaf(sa, v0, sbb), 0.f);
                    v1 = fmaxf(fmaf(sa, v1, sbb), 0.f);
                }
                if (rp) {
                    float2 rr = *(const float2*)(rp + nt * 8);
                    v0 += rr.x; v1 += rr.y;
                }
                *(float2*)(cp_ + nt * 8) = make_float2(v0, v1);
            }
        }
    }
}

// ---------------------------------------------------------------------------
// scores[bh, n, m] = (1/8) * sum_dk Q[b, dk*H+h, n] * K[b, dk*H+h, m]
// ---------------------------------------------------------------------------
__global__ __launch_bounds__(256)
void scores_k(const float* __restrict__ Q, const float* __restrict__ Kk,
              float* __restrict__ S)
{
    __shared__ float Qs[64][64];
    __shared__ float Ks[64][64];
    const int tid = threadIdx.x;
    const int tx = tid & 15, ty = tid >> 4;
    const int n0 = blockIdx.x * 64;
    const int m0 = blockIdx.y * 64;
    const int bh = blockIdx.z;
    const int b = bh >> 4, h = bh & 15;
    const float* qb = Q + (long)b * (DIM * NN) + h * NN;
    const float* kb = Kk + (long)b * (DIM * NN) + h * NN;

    const int dkr = tid >> 4, col = (tid & 15) * 4;
#pragma unroll
    for (int r = 0; r < 4; r++) {
        const int dk = dkr + 16 * r;
        *(float4*)&Qs[dk][col] = *(const float4*)(qb + (long)dk * (HEADS * NN) + n0 + col);
        *(float4*)&Ks[dk][col] = *(const float4*)(kb + (long)dk * (HEADS * NN) + m0 + col);
    }
    __syncthreads();

    float acc[4][4];
#pragma unroll
    for (int ii = 0; ii < 4; ii++)
#pragma unroll
        for (int jj = 0; jj < 4; jj++) acc[ii][jj] = 0.f;

#pragma unroll 8
    for (int dk = 0; dk < 64; dk++) {
        float4 a  = *(const float4*)&Qs[dk][ty * 4];
        float4 bv = *(const float4*)&Ks[dk][tx * 4];
        float av[4] = {a.x, a.y, a.z, a.w};
        float bb[4] = {bv.x, bv.y, bv.z, bv.w};
#pragma unroll
        for (int ii = 0; ii < 4; ii++)
#pragma unroll
            for (int jj = 0; jj < 4; jj++)
                acc[ii][jj] = fmaf(av[ii], bb[jj], acc[ii][jj]);
    }

    float* sb = S + (long)bh * NN * NN;
    const float sc = 0.125f;
#pragma unroll
    for (int ii = 0; ii < 4; ii++) {
        const int n = n0 + ty * 4 + ii;
        *(float4*)(sb + (long)n * NN + m0 + tx * 4) =
            make_float4(acc[ii][0] * sc, acc[ii][1] * sc,
                        acc[ii][2] * sc, acc[ii][3] * sc);
    }
}

__global__ __launch_bounds__(256)
void softmax_k(float* __restrict__ S)
{
    float* p = S + (long)blockIdx.x * NN;
    const int tid = threadIdx.x;
    float4 v = *(float4*)(p + tid * 4);

    float m = fmaxf(fmaxf(v.x, v.y), fmaxf(v.z, v.w));
#pragma unroll
    for (int o = 16; o; o >>= 1) m = fmaxf(m, __shfl_xor_sync(0xffffffffu, m, o));
    __shared__ float red[8];
    const int wid = tid >> 5, lid = tid & 31;
    if (lid == 0) red[wid] = m;
    __syncthreads();
    float mm = red[0];
#pragma unroll
    for (int i = 1; i < 8; i++) mm = fmaxf(mm, red[i]);
    __syncthreads();

    v.x = __expf(v.x - mm); v.y = __expf(v.y - mm);
    v.z = __expf(v.z - mm); v.w = __expf(v.w - mm);
    float s = v.x + v.y + v.z + v.w;
#pragma unroll
    for (int o = 16; o; o >>= 1) s += __shfl_xor_sync(0xffffffffu, s, o);
    if (lid == 0) red[wid] = s;
    __syncthreads();
    float tot = red[0];
#pragma unroll
    for (int i = 1; i < 8; i++) tot += red[i];
    const float inv = 1.f / tot;
    v.x *= inv; v.y *= inv; v.z *= inv; v.w *= inv;
    *(float4*)(p + tid * 4) = v;
}

__global__ __launch_bounds__(256)
void attnout_k(const float* __restrict__ W, const float* __restrict__ V,
               float* __restrict__ O)
{
    __shared__ float Vs[64][68];
    __shared__ float Ws[64][68];
    const int tid = threadIdx.x;
    const int tx = tid & 15, ty = tid >> 4;
    const int n0 = blockIdx.x * 64;
    const int bh = blockIdx.y;
    const int b = bh >> 4, h = bh & 15;
    const float* vb = V + (long)b * (DIM * NN) + h * NN;
    const float* wb = W + (long)bh * NN * NN;

    float acc[4][4];
#pragma unroll
    for (int ii = 0; ii < 4; ii++)
#pragma unroll
        for (int jj = 0; jj < 4; jj++) acc[ii][jj] = 0.f;

    const int rr = tid >> 4, col = (tid & 15) * 4;
    for (int m0 = 0; m0 < NN; m0 += 64) {
#pragma unroll
        for (int r = 0; r < 4; r++) {
            const int q = rr + 16 * r;
            *(float4*)&Vs[q][col] = *(const float4*)(vb + (long)q * (HEADS * NN) + m0 + col);
            *(float4*)&Ws[q][col] = *(const float4*)(wb + (long)(n0 + q) * NN + m0 + col);
        }
        __syncthreads();
#pragma unroll 8
        for (int mm = 0; mm < 64; mm++) {
            float av[4], bv[4];
#pragma unroll
            for (int ii = 0; ii < 4; ii++) av[ii] = Vs[ty * 4 + ii][mm];
#pragma unroll
            for (int jj = 0; jj < 4; jj++) bv[jj] = Ws[tx * 4 + jj][mm];
#pragma unroll
            for (int ii = 0; ii < 4; ii++)
#pragma unroll
                for (int jj = 0; jj < 4; jj++)
                    acc[ii][jj] = fmaf(av[ii], bv[jj], acc[ii][jj]);
        }
        __syncthreads();
    }

    float* ob = O + (long)b * (DIM * NN) + h * NN;
#pragma unroll
    for (int ii = 0; ii < 4; ii++) {
        const int dk = ty * 4 + ii;
        *(float4*)(ob + (long)dk * (HEADS * NN) + n0 + tx * 4) =
            make_float4(acc[ii][0], acc[ii][1], acc[ii][2], acc[ii][3]);
    }
}

// ---------------------------------------------------------------------------
// Host launch
// ---------------------------------------------------------------------------
extern "C" void kernel_launch(void* const* d_in, const int* in_sizes, int n_in,
                              void* d_out, int out_size)
{
    const float* motion = (const float*)d_in[0];
    const float* Wq = (const float*)d_in[1];
    const float* bq = (const float*)d_in[2];
    const float* Wk = (const float*)d_in[3];
    const float* bk = (const float*)d_in[4];
    const float* Wv = (const float*)d_in[5];
    const float* bv = (const float*)d_in[6];
    const float* Wm = (const float*)d_in[7];
    const float* bm = (const float*)d_in[8];
    const float* Wp1 = (const float*)d_in[9];
    const float* bp1 = (const float*)d_in[10];
    const float* bng = (const float*)d_in[11];
    const float* bnb = (const float*)d_in[12];
    const float* bnm = (const float*)d_in[13];
    const float* bnv = (const float*)d_in[14];
    const float* Wp2 = (const float*)d_in[15];
    const float* bp2 = (const float*)d_in[16];
    float* out = (float*)d_out;

    float *Qb, *Kb, *Vb, *ATT, *MRG, *H1, *X0, *X1, *S;
    cudaGetSymbolAddress((void**)&Qb,  g_Q);
    cudaGetSymbolAddress((void**)&Kb,  g_K);
    cudaGetSymbolAddress((void**)&Vb,  g_V);
    cudaGetSymbolAddress((void**)&ATT, g_ATT);
    cudaGetSymbolAddress((void**)&MRG, g_MRG);
    cudaGetSymbolAddress((void**)&H1,  g_H1);
    cudaGetSymbolAddress((void**)&X0,  g_X0);
    cudaGetSymbolAddress((void**)&X1,  g_X1);
    cudaGetSymbolAddress((void**)&S,   g_S);

    __nv_bfloat16 *WqH, *WqL, *WkH, *WkL, *WvH, *WvL, *WmH, *WmL, *W1H, *W1L, *W2H, *W2L;
    __nv_bfloat16 *XTh, *XTl, *ATh, *ATl, *MTh, *MTl, *HTh, *HTl;
    cudaGetSymbolAddress((void**)&WqH, g_WqH); cudaGetSymbolAddress((void**)&WqL, g_WqL);
    cudaGetSymbolAddress((void**)&WkH, g_WkH); cudaGetSymbolAddress((void**)&WkL, g_WkL);
    cudaGetSymbolAddress((void**)&WvH, g_WvH); cudaGetSymbolAddress((void**)&WvL, g_WvL);
    cudaGetSymbolAddress((void**)&WmH, g_WmH); cudaGetSymbolAddress((void**)&WmL, g_WmL);
    cudaGetSymbolAddress((void**)&W1H, g_W1H); cudaGetSymbolAddress((void**)&W1L, g_W1L);
    cudaGetSymbolAddress((void**)&W2H, g_W2H); cudaGetSymbolAddress((void**)&W2L, g_W2L);
    cudaGetSymbolAddress((void**)&XTh, g_XTh); cudaGetSymbolAddress((void**)&XTl, g_XTl);
    cudaGetSymbolAddress((void**)&ATh, g_ATh); cudaGetSymbolAddress((void**)&ATl, g_ATl);
    cudaGetSymbolAddress((void**)&MTh, g_MTh); cudaGetSymbolAddress((void**)&MTl, g_MTl);
    cudaGetSymbolAddress((void**)&HTh, g_HTh); cudaGetSymbolAddress((void**)&HTl, g_HTl);

    cudaFuncSetAttribute(mma_gemm, cudaFuncAttributeMaxDynamicSharedMemorySize, MG_SMEM);

    // weight conversions (all layers)
    const int nDD  = LAYERS * DIM * DIM;
    const int n2D2 = LAYERS * TWOD * TWOD;
    const int nD2  = LAYERS * DIM * TWOD;
    cvt_w<<<nDD / 1024, 256>>>(Wq, WqH, WqL, nDD);
    cvt_w<<<nDD / 1024, 256>>>(Wk, WkH, WkL, nDD);
    cvt_w<<<nDD / 1024, 256>>>(Wv, WvH, WvL, nDD);
    cvt_w<<<nDD / 1024, 256>>>(Wm, WmH, WmL, nDD);
    cvt_w<<<n2D2 / 1024, 256>>>(Wp1, W1H, W1L, n2D2);
    cvt_w<<<nD2 / 1024, 256>>>(Wp2, W2H, W2L, nD2);

    const dim3 gT1(NN / 32, DIM / 32, BATCH);
    const dim3 gT2(NN / 32, TWOD / 32, BATCH);
    const dim3 blkT(32, 8);
    const dim3 gG1(32, DIM / 128);    // 32 n-blocks x 8 m-blocks
    const dim3 gG2(32, TWOD / 128);
    const dim3 gScores(NN / 64, NN / 64, BATCH * HEADS);
    const dim3 gAttn(NN / 64, BATCH * HEADS);
    const long cbs1 = (long)DIM * NN;
    const long cbs2 = (long)TWOD * NN;

    for (int l = 0; l < LAYERS; l++) {
        const float* xin = (l == 0) ? motion : ((l & 1) ? X1 : X0);
        float* xout = (l == 3) ? out : ((l & 1) ? X0 : X1);
        const long oDD = (long)l * DIM * DIM;
        const long o2D2 = (long)l * TWOD * TWOD;
        const long oD2 = (long)l * DIM * TWOD;

        // x -> transposed bf16 hi/lo
        tcvt<<<gT1, blkT>>>(xin, XTh, XTl, DIM);

        // Q, K, V projections
        mma_gemm<<<gG1, 256, MG_SMEM>>>(WqH + oDD, WqL + oDD, DIM,
                                        XTh, XTl, DIM, 32, XTh, XTl, DIM, 32,
                                        bq + l * DIM, nullptr, nullptr, nullptr, nullptr,
                                        nullptr, Qb, cbs1);
        mma_gemm<<<gG1, 256, MG_SMEM>>>(WkH + oDD, WkL + oDD, DIM,
                                        XTh, XTl, DIM, 32, XTh, XTl, DIM, 32,
                                        bk + l * DIM, nullptr, nullptr, nullptr, nullptr,
                                        nullptr, Kb, cbs1);
        mma_gemm<<<gG1, 256, MG_SMEM>>>(WvH + oDD, WvL + oDD, DIM,
                                        XTh, XTl, DIM, 32, XTh, XTl, DIM, 32,
                                        bv + l * DIM, nullptr, nullptr, nullptr, nullptr,
                                        nullptr, Vb, cbs1);

        // Attention (SIMT fp32)
        scores_k<<<gScores, 256>>>(Qb, Kb, S);
        softmax_k<<<BATCH * HEADS * NN, 256>>>(S);
        attnout_k<<<gAttn, 256>>>(S, Vb, ATT);

        // merge
        tcvt<<<gT1, blkT>>>(ATT, ATh, ATl, DIM);
        mma_gemm<<<gG1, 256, MG_SMEM>>>(WmH + oDD, WmL + oDD, DIM,
                                        ATh, ATl, DIM, 32, ATh, ATl, DIM, 32,
                                        bm + l * DIM, nullptr, nullptr, nullptr, nullptr,
                                        nullptr, MRG, cbs1);

        // p1: Wp1 @ concat(merged, x) + bias -> BN -> ReLU  (K split at chunk 32)
        tcvt<<<gT1, blkT>>>(MRG, MTh, MTl, DIM);
        mma_gemm<<<gG2, 256, MG_SMEM>>>(W1H + o2D2, W1L + o2D2, TWOD,
                                        MTh, MTl, DIM, 32, XTh, XTl, DIM, 64,
                                        bp1 + l * TWOD,
                                        bng + l * TWOD, bnb + l * TWOD,
                                        bnm + l * TWOD, bnv + l * TWOD,
                                        nullptr, H1, cbs2);

        // p2: Wp2 @ h + bias + residual
        tcvt<<<gT2, blkT>>>(H1, HTh, HTl, TWOD);
        mma_gemm<<<gG1, 256, MG_SMEM>>>(W2H + oD2, W2L + oD2, TWOD,
                                        HTh, HTl, TWOD, 64, HTh, HTl, TWOD, 64,
                                        bp2 + l * DIM, nullptr, nullptr, nullptr, nullptr,
                                        xin, xout, cbs1);
    }
}

// round 12
// speedup vs baseline: 2.8339x; 1.5852x over previous
#include <cuda_runtime.h>
#include <cuda_bf16.h>
#include <cstdint>

#define BATCH 4
#define DIM   1024
#define HEADS 16
#define DK    64
#define NN    1024
#define LAYERS 4
#define TWOD  2048
#define BN_EPS 1e-5f

// ---------------------------------------------------------------------------
// Scratch (device globals — no allocation allowed)
// ---------------------------------------------------------------------------
__device__ float g_Q  [BATCH * DIM * NN];
__device__ float g_K  [BATCH * DIM * NN];
__device__ float g_V  [BATCH * DIM * NN];
__device__ float g_MRG[BATCH * DIM * NN];
__device__ float g_H1 [BATCH * TWOD * NN];
__device__ float g_X0 [BATCH * DIM * NN];
__device__ float g_X1 [BATCH * DIM * NN];

// bf16 hi/lo weight copies (converted each call)
__device__ __nv_bfloat16 g_WqH[LAYERS * DIM * DIM],  g_WqL[LAYERS * DIM * DIM];
__device__ __nv_bfloat16 g_WkH[LAYERS * DIM * DIM],  g_WkL[LAYERS * DIM * DIM];
__device__ __nv_bfloat16 g_WvH[LAYERS * DIM * DIM],  g_WvL[LAYERS * DIM * DIM];
__device__ __nv_bfloat16 g_WmH[LAYERS * DIM * DIM],  g_WmL[LAYERS * DIM * DIM]; // col-permuted
__device__ __nv_bfloat16 g_W1H[LAYERS * TWOD * TWOD], g_W1L[LAYERS * TWOD * TWOD];
__device__ __nv_bfloat16 g_W2H[LAYERS * DIM * TWOD],  g_W2L[LAYERS * DIM * TWOD];

// bf16 hi/lo transposed activations: [b][n][k]
__device__ __nv_bfloat16 g_XTh[BATCH * NN * DIM],  g_XTl[BATCH * NN * DIM];
__device__ __nv_bfloat16 g_MTh[BATCH * NN * DIM],  g_MTl[BATCH * NN * DIM];
__device__ __nv_bfloat16 g_HTh[BATCH * NN * TWOD], g_HTl[BATCH * NN * TWOD];
// attention operands: QT/KT per-head [bh][n][64]; VT channel-major [b][c][m]
__device__ __nv_bfloat16 g_QTh[BATCH * HEADS * NN * DK], g_QTl[BATCH * HEADS * NN * DK];
__device__ __nv_bfloat16 g_KTh[BATCH * HEADS * NN * DK], g_KTl[BATCH * HEADS * NN * DK];
__device__ __nv_bfloat16 g_VTh[BATCH * DIM * NN], g_VTl[BATCH * DIM * NN];
// flash output, head-blocked channels: [b][n][h*64+dk]
__device__ __nv_bfloat16 g_OTh[BATCH * NN * DIM], g_OTl[BATCH * NN * DIM];

// ---------------------------------------------------------------------------
// PTX helpers (base sm_80+ ISA only — no tcgen05 on this build target)
// ---------------------------------------------------------------------------
__device__ __forceinline__ uint32_t smem_u32(const void* p) {
    return (uint32_t)__cvta_generic_to_shared(p);
}
__device__ __forceinline__ void cpa16(uint32_t dst, const void* src) {
    asm volatile("cp.async.cg.shared.global [%0], [%1], 16;"
                 :: "r"(dst), "l"(__cvta_generic_to_global(src)) : "memory");
}
#define CP_COMMIT() asm volatile("cp.async.commit_group;" ::: "memory")
#define CP_WAIT1()  asm volatile("cp.async.wait_group 1;" ::: "memory")
#define CP_WAIT0()  asm volatile("cp.async.wait_group 0;" ::: "memory")

__device__ __forceinline__ void ldm4(uint32_t& r0, uint32_t& r1, uint32_t& r2,
                                     uint32_t& r3, uint32_t addr) {
    asm volatile("ldmatrix.sync.aligned.m8n8.x4.shared.b16 {%0,%1,%2,%3}, [%4];"
                 : "=r"(r0), "=r"(r1), "=r"(r2), "=r"(r3) : "r"(addr));
}
__device__ __forceinline__ void mma_bf16(float& c0, float& c1, float& c2, float& c3,
                                         uint32_t a0, uint32_t a1, uint32_t a2,
                                         uint32_t a3, uint32_t b0, uint32_t b1) {
    asm volatile("mma.sync.aligned.m16n8k16.row.col.f32.bf16.bf16.f32 "
                 "{%0,%1,%2,%3}, {%4,%5,%6,%7}, {%8,%9}, {%0,%1,%2,%3};"
                 : "+f"(c0), "+f"(c1), "+f"(c2), "+f"(c3)
                 : "r"(a0), "r"(a1), "r"(a2), "r"(a3), "r"(b0), "r"(b1));
}
// pack two f32 -> bf16x2 {lo, hi}
__device__ __forceinline__ uint32_t packbf(float lo, float hi) {
    uint32_t r;
    asm("cvt.rn.bf16x2.f32 %0, %1, %2;" : "=r"(r) : "f"(hi), "f"(lo));
    return r;
}
__device__ __forceinline__ uint32_t packlo(float lo, float hi) {
    float rl = lo - __bfloat162float(__float2bfloat16(lo));
    float rh = hi - __bfloat162float(__float2bfloat16(hi));
    return packbf(rl, rh);
}

// ---------------------------------------------------------------------------
// Conversion: fp32 -> bf16 hi/lo split
// ---------------------------------------------------------------------------
__device__ __forceinline__ void split2(float x, __nv_bfloat16& h, __nv_bfloat16& l) {
    h = __float2bfloat16(x);
    l = __float2bfloat16(x - __bfloat162float(h));
}

__global__ __launch_bounds__(256)
void cvt_w(const float* __restrict__ w, __nv_bfloat16* __restrict__ hi,
           __nv_bfloat16* __restrict__ lo, int n)
{
    int i = (blockIdx.x * 256 + threadIdx.x) * 4;
    if (i >= n) return;
    float4 v = *(const float4*)(w + i);
    split2(v.x, hi[i + 0], lo[i + 0]);
    split2(v.y, hi[i + 1], lo[i + 1]);
    split2(v.z, hi[i + 2], lo[i + 2]);
    split2(v.w, hi[i + 3], lo[i + 3]);
}

// merge weight: permute input channels c = dk*16+h -> c' = h*64+dk
__global__ __launch_bounds__(256)
void cvt_wm(const float* __restrict__ w, __nv_bfloat16* __restrict__ hi,
            __nv_bfloat16* __restrict__ lo, int n)
{
    int i = (blockIdx.x * 256 + threadIdx.x) * 4;
    if (i >= n) return;
    int rowbase = i & ~1023;
#pragma unroll
    for (int u = 0; u < 4; u++) {
        int jp = (i + u) & 1023;              // c' = h*64+dk
        int j = ((jp & 63) << 4) | (jp >> 6); // c  = dk*16+h
        split2(w[rowbase + j], hi[i + u], lo[i + u]);
    }
}

// Transpose + convert: in [b][K][NN] fp32 -> out [b][NN][K] bf16 hi/lo
__global__ __launch_bounds__(256)
void tcvt(const float* __restrict__ in, __nv_bfloat16* __restrict__ hi,
          __nv_bfloat16* __restrict__ lo, int K)
{
    __shared__ float t[32][33];
    const int b = blockIdx.z;
    const float* ip = in + (long)b * K * NN;
    __nv_bfloat16* hp = hi + (long)b * NN * K;
    __nv_bfloat16* lp = lo + (long)b * NN * K;
    const int n0 = blockIdx.x * 32, k0 = blockIdx.y * 32;
    const int tx = threadIdx.x, ty = threadIdx.y;  // (32, 8)
#pragma unroll
    for (int r = 0; r < 4; r++) {
        int kk = ty + r * 8;
        t[kk][tx] = ip[(long)(k0 + kk) * NN + n0 + tx];
    }
    __syncthreads();
#pragma unroll
    for (int r = 0; r < 4; r++) {
        int nn = ty + r * 8;
        float v = t[tx][nn];
        long o = (long)(n0 + nn) * K + k0 + tx;
        split2(v, hp[o], lp[o]);
    }
}

// Per-head transpose + convert: in fp32 [b][dk*16+h][n] -> out [bh][n][64] hi/lo
__global__ __launch_bounds__(256)
void qk_tcvt(const float* __restrict__ in, __nv_bfloat16* __restrict__ hi,
             __nv_bfloat16* __restrict__ lo, float scale)
{
    __shared__ float t[32][33];
    const int bh = blockIdx.z, b = bh >> 4, h = bh & 15;
    const int n0 = blockIdx.x * 32, d0 = blockIdx.y * 32;
    const int tx = threadIdx.x, ty = threadIdx.y;  // (32, 8)
    const float* ip = in + (long)b * DIM * NN;
#pragma unroll
    for (int r = 0; r < 4; r++) {
        int kk = ty + r * 8;
        t[kk][tx] = ip[(long)((d0 + kk) * 16 + h) * NN + n0 + tx];
    }
    __syncthreads();
    __nv_bfloat16* hp = hi + (long)bh * NN * DK;
    __nv_bfloat16* lp = lo + (long)bh * NN * DK;
#pragma unroll
    for (int r = 0; r < 4; r++) {
        int nn = ty + r * 8;
        float v = t[tx][nn] * scale;
        long o = (long)(n0 + nn) * DK + d0 + tx;
        split2(v, hp[o], lp[o]);
    }
}

// ---------------------------------------------------------------------------
// HMMA GEMM (validated in R5): C[b,i,n0+j] = sum_k A[i,k]*B[b,j,k]
// ---------------------------------------------------------------------------
#define MG_SMEM (2 * 32768)

__global__ __launch_bounds__(256, 1)
void mma_gemm(const __nv_bfloat16* __restrict__ Ah, const __nv_bfloat16* __restrict__ Al,
              int lda,
              const __nv_bfloat16* __restrict__ B1h, const __nv_bfloat16* __restrict__ B1l,
              int ldb1, int nc1,
              const __nv_bfloat16* __restrict__ B2h, const __nv_bfloat16* __restrict__ B2l,
              int ldb2, int nctot,
              const float* __restrict__ bias,
              const float* __restrict__ bng, const float* __restrict__ bnb,
              const float* __restrict__ bnm, const float* __restrict__ bnv,
              const float* __restrict__ res, float* __restrict__ C, long cbs)
{
    extern __shared__ __align__(128) char dsm[];
    const uint32_t smem_base = smem_u32(dsm);

    const int tid = threadIdx.x;
    const int wid = tid >> 5, lid = tid & 31;
    const int warp_m = wid & 1;
    const int warp_n = wid >> 1;
    const int j0 = blockIdx.x * 128;
    const int b  = j0 >> 10;
    const int n0 = j0 & 1023;
    const int i0 = blockIdx.y * 128;

    const __nv_bfloat16* b1h = B1h + (long)b * NN * ldb1;
    const __nv_bfloat16* b1l = B1l + (long)b * NN * ldb1;
    const __nv_bfloat16* b2h = B2h + (long)b * NN * ldb2;
    const __nv_bfloat16* b2l = B2l + (long)b * NN * ldb2;

    const int frow = ((lid >> 3) & 1) * 8 + (lid & 7);
    const int fchk = lid >> 4;
    uint32_t offA[4][2], offB[2][2];
#pragma unroll
    for (int mt = 0; mt < 4; mt++) {
        const int row = warp_m * 64 + mt * 16 + frow;
#pragma unroll
        for (int s16 = 0; s16 < 2; s16++) {
            const int ch = s16 * 2 + fchk;
            offA[mt][s16] = row * 64 + ((ch ^ ((row >> 1) & 3)) << 4);
        }
    }
#pragma unroll
    for (int np = 0; np < 2; np++) {
        const int row = warp_n * 32 + np * 16 + frow;
#pragma unroll
        for (int s16 = 0; s16 < 2; s16++) {
            const int ch = s16 * 2 + fchk;
            offB[np][s16] = row * 64 + ((ch ^ ((row >> 1) & 3)) << 4);
        }
    }

    float acc[4][4][4];
#pragma unroll
    for (int mt = 0; mt < 4; mt++)
#pragma unroll
        for (int nt = 0; nt < 4; nt++)
#pragma unroll
            for (int q = 0; q < 4; q++) acc[mt][nt][q] = 0.f;

    auto load_stage = [&](int c, int s) {
        const uint32_t sb = smem_base + s * 32768;
        const __nv_bfloat16 *pbh, *pbl;
        long kb;
        int ldb;
        if (c < nc1) { pbh = b1h; pbl = b1l; ldb = ldb1; kb = (long)c * 32; }
        else         { pbh = b2h; pbl = b2l; ldb = ldb2; kb = (long)(c - nc1) * 32; }
#pragma unroll
        for (int it = 0; it < 2; it++) {
            const int si = it * 256 + tid;
            const int row = si >> 2, ch = si & 3;
            const uint32_t dsw = row * 64 + ((ch ^ ((row >> 1) & 3)) << 4);
            cpa16(sb + dsw,          Ah + (long)(i0 + row) * lda + (long)c * 32 + ch * 8);
            cpa16(sb + 8192 + dsw,   Al + (long)(i0 + row) * lda + (long)c * 32 + ch * 8);
            cpa16(sb + 16384 + dsw,  pbh + (long)(n0 + row) * ldb + kb + ch * 8);
            cpa16(sb + 24576 + dsw,  pbl + (long)(n0 + row) * ldb + kb + ch * 8);
        }
    };

    load_stage(0, 0);
    CP_COMMIT();

    for (int c = 0; c < nctot; c++) {
        if (c + 1 < nctot) {
            load_stage(c + 1, (c + 1) & 1);
            CP_COMMIT();
            CP_WAIT1();
        } else {
            CP_WAIT0();
        }
        __syncthreads();

        const uint32_t sb  = smem_base + (c & 1) * 32768;
        const uint32_t sAh = sb, sAl = sb + 8192, sBh = sb + 16384, sBl = sb + 24576;
#pragma unroll
        for (int s16 = 0; s16 < 2; s16++) {
            uint32_t ah[4][4], al_[4][4], bh[2][4], bl[2][4];
#pragma unroll
            for (int mt = 0; mt < 4; mt++) {
                ldm4(ah[mt][0], ah[mt][1], ah[mt][2], ah[mt][3], sAh + offA[mt][s16]);
                ldm4(al_[mt][0], al_[mt][1], al_[mt][2], al_[mt][3], sAl + offA[mt][s16]);
            }
#pragma unroll
            for (int np = 0; np < 2; np++) {
                ldm4(bh[np][0], bh[np][1], bh[np][2], bh[np][3], sBh + offB[np][s16]);
                ldm4(bl[np][0], bl[np][1], bl[np][2], bl[np][3], sBl + offB[np][s16]);
            }
#pragma unroll
            for (int mt = 0; mt < 4; mt++) {
#pragma unroll
                for (int nt = 0; nt < 4; nt++) {
                    const int np = nt >> 1, o = nt & 1;
                    float* a = acc[mt][nt];
                    mma_bf16(a[0], a[1], a[2], a[3],
                             ah[mt][0], ah[mt][1], ah[mt][2], ah[mt][3],
                             bh[np][o], bh[np][o + 2]);
                    mma_bf16(a[0], a[1], a[2], a[3],
                             ah[mt][0], ah[mt][1], ah[mt][2], ah[mt][3],
                             bl[np][o], bl[np][o + 2]);
                    mma_bf16(a[0], a[1], a[2], a[3],
                             al_[mt][0], al_[mt][1], al_[mt][2], al_[mt][3],
                             bh[np][o], bh[np][o + 2]);
                }
            }
        }
        __syncthreads();
    }

    const int g = lid >> 2, t = lid & 3;
    const bool bn = (bng != nullptr);
#pragma unroll
    for (int mt = 0; mt < 4; mt++) {
#pragma unroll
        for (int half = 0; half < 2; half++) {
            const int r = i0 + warp_m * 64 + mt * 16 + g + half * 8;
            const float bi = bias[r];
            float sa = 0.f, sbb = 0.f;
            if (bn) {
                const float inv = rsqrtf(bnv[r] + BN_EPS);
                sa = bng[r] * inv;
                sbb = bnb[r] - sa * bnm[r];
            }
            float* cp_ = C + (long)b * cbs + (long)r * NN + n0 + warp_n * 32 + t * 2;
            const float* rp = res ? res + (long)b * ((long)DIM * NN) + (long)r * NN
                                        + n0 + warp_n * 32 + t * 2
                                  : nullptr;
#pragma unroll
            for (int nt = 0; nt < 4; nt++) {
                float v0 = acc[mt][nt][half * 2 + 0] + bi;
                float v1 = acc[mt][nt][half * 2 + 1] + bi;
                if (bn) {
                    v0 = fmaxf(fmaf(sa, v0, sbb), 0.f);
                    v1 = fmaxf(fmaf(sa, v1, sbb), 0.f);
                }
                if (rp) {
                    float2 rr = *(const float2*)(rp + nt * 8);
                    v0 += rr.x; v1 += rr.y;
                }
                *(float2*)(cp_ + nt * 8) = make_float2(v0, v1);
            }
        }
    }
}

// ---------------------------------------------------------------------------
// Flash attention (HMMA, hi/lo). Grid (NN/128, B*H), 256 threads.
// Register-lean variant: S processed in two 64-col halves per 128-col KV
// chunk (s[8][4] live instead of s[16][4]); KV loop NOT unrolled to keep
// code size and ptxas time bounded.
// Q pre-scaled by 1/8. Output: [b][n][h*64+dk] bf16 hi/lo.
// ---------------------------------------------------------------------------
#define FL_SMEM (6 * 16384)

__global__ __launch_bounds__(256, 1)
void flash_k(const __nv_bfloat16* __restrict__ QTh, const __nv_bfloat16* __restrict__ QTl,
             const __nv_bfloat16* __restrict__ KTh, const __nv_bfloat16* __restrict__ KTl,
             const __nv_bfloat16* __restrict__ Vh,  const __nv_bfloat16* __restrict__ Vl,
             __nv_bfloat16* __restrict__ Oh, __nv_bfloat16* __restrict__ Ol)
{
    extern __shared__ __align__(128) char fsm[];
    const uint32_t base = smem_u32(fsm);
    const int tid = threadIdx.x, wid = tid >> 5, lid = tid & 31;
    const int n0 = blockIdx.x * 128;
    const int bh = blockIdx.y;
    const int b = bh >> 4, h = bh & 15;

    const uint32_t sQh = base,          sQl = base + 16384;
    const uint32_t sKh = base + 32768,  sKl = base + 49152;
    const uint32_t sVh = base + 65536,  sVl = base + 81920;

    // ---- load Q tile [n128][dk64] ----
    const __nv_bfloat16* qhp = QTh + (long)bh * NN * DK;
    const __nv_bfloat16* qlp = QTl + (long)bh * NN * DK;
#pragma unroll
    for (int it = 0; it < 4; it++) {
        const int si = it * 256 + tid;
        const int row = si >> 3, ch = si & 7;
        const uint32_t d = row * 128 + ((ch ^ (row & 7)) << 4);
        cpa16(sQh + d, qhp + (long)(n0 + row) * DK + ch * 8);
        cpa16(sQl + d, qlp + (long)(n0 + row) * DK + ch * 8);
    }
    CP_COMMIT(); CP_WAIT0(); __syncthreads();

    const int frow = ((lid >> 3) & 1) * 8 + (lid & 7);
    const int fchk = lid >> 4;

    // Q fragments (loop invariant): 4 k-steps
    uint32_t qh[4][4], ql[4][4];
#pragma unroll
    for (int ks = 0; ks < 4; ks++) {
        const int row = wid * 16 + frow;
        const uint32_t off = row * 128 + ((((ks << 1) + fchk) ^ (row & 7)) << 4);
        ldm4(qh[ks][0], qh[ks][1], qh[ks][2], qh[ks][3], sQh + off);
        ldm4(ql[ks][0], ql[ks][1], ql[ks][2], ql[ks][3], sQl + off);
    }

    float oacc[8][4];
#pragma unroll
    for (int j = 0; j < 8; j++)
#pragma unroll
        for (int q = 0; q < 4; q++) oacc[j][q] = 0.f;
    float mrow0 = -1e30f, mrow1 = -1e30f;
    float lrow0 = 0.f, lrow1 = 0.f;

    const __nv_bfloat16* khp = KTh + (long)bh * NN * DK;
    const __nv_bfloat16* klp = KTl + (long)bh * NN * DK;
    const __nv_bfloat16* vhp = Vh + (long)b * DIM * NN + (long)h * NN;
    const __nv_bfloat16* vlp = Vl + (long)b * DIM * NN + (long)h * NN;

#pragma unroll 1
    for (int c0 = 0; c0 < NN; c0 += 128) {
        __syncthreads();   // previous chunk's smem reads done
        // ---- load K chunk [m128][dk64] ----
#pragma unroll
        for (int it = 0; it < 4; it++) {
            const int si = it * 256 + tid;
            const int row = si >> 3, ch = si & 7;
            const uint32_t d = row * 128 + ((ch ^ (row & 7)) << 4);
            cpa16(sKh + d, khp + (long)(c0 + row) * DK + ch * 8);
            cpa16(sKl + d, klp + (long)(c0 + row) * DK + ch * 8);
        }
        // ---- load V chunk [dk64][m128] (channel-major source) ----
#pragma unroll
        for (int it = 0; it < 4; it++) {
            const int si = it * 256 + tid;
            const int row = si >> 4, ch = si & 15;
            const uint32_t d = row * 256 + ((ch ^ (row & 15)) << 4);
            cpa16(sVh + d, vhp + (long)row * (HEADS * NN) + c0 + ch * 8);
            cpa16(sVl + d, vlp + (long)row * (HEADS * NN) + c0 + ch * 8);
        }
        CP_COMMIT(); CP_WAIT0(); __syncthreads();

#pragma unroll 1
        for (int half = 0; half < 2; half++) {
            // ---- S_half = Q K^T over 64 m-cols (3-pass hi/lo) ----
            float s[8][4];
#pragma unroll
            for (int j = 0; j < 8; j++)
#pragma unroll
                for (int q = 0; q < 4; q++) s[j][q] = 0.f;

#pragma unroll
            for (int g8 = 0; g8 < 4; g8++) {
                uint32_t kh4[4][4], kl4[4][4];
#pragma unroll
                for (int ks = 0; ks < 4; ks++) {
                    const int row = half * 64 + g8 * 16 + frow;
                    const uint32_t off = row * 128 + ((((ks << 1) + fchk) ^ (row & 7)) << 4);
                    ldm4(kh4[ks][0], kh4[ks][1], kh4[ks][2], kh4[ks][3], sKh + off);
                    ldm4(kl4[ks][0], kl4[ks][1], kl4[ks][2], kl4[ks][3], sKl + off);
                }
#pragma unroll
                for (int o = 0; o < 2; o++) {
                    float* a = s[g8 * 2 + o];
#pragma unroll
                    for (int ks = 0; ks < 4; ks++) {
                        mma_bf16(a[0], a[1], a[2], a[3],
                                 qh[ks][0], qh[ks][1], qh[ks][2], qh[ks][3],
                                 kh4[ks][o], kh4[ks][o + 2]);
                        mma_bf16(a[0], a[1], a[2], a[3],
                                 qh[ks][0], qh[ks][1], qh[ks][2], qh[ks][3],
                                 kl4[ks][o], kl4[ks][o + 2]);
                        mma_bf16(a[0], a[1], a[2], a[3],
                                 ql[ks][0], ql[ks][1], ql[ks][2], ql[ks][3],
                                 kh4[ks][o], kh4[ks][o + 2]);
                    }
                }
            }

            // ---- online softmax update (rows: pair 0 = g, pair 1 = g+8) ----
            float cm0 = -1e30f, cm1 = -1e30f;
#pragma unroll
            for (int j = 0; j < 8; j++) {
                cm0 = fmaxf(cm0, fmaxf(s[j][0], s[j][1]));
                cm1 = fmaxf(cm1, fmaxf(s[j][2], s[j][3]));
            }
            cm0 = fmaxf(cm0, __shfl_xor_sync(0xffffffffu, cm0, 1));
            cm0 = fmaxf(cm0, __shfl_xor_sync(0xffffffffu, cm0, 2));
            cm1 = fmaxf(cm1, __shfl_xor_sync(0xffffffffu, cm1, 1));
            cm1 = fmaxf(cm1, __shfl_xor_sync(0xffffffffu, cm1, 2));
            const float mn0 = fmaxf(mrow0, cm0);
            const float mn1 = fmaxf(mrow1, cm1);
            const float al0 = __expf(mrow0 - mn0);
            const float al1 = __expf(mrow1 - mn1);
            mrow0 = mn0; mrow1 = mn1;

            float ps0 = 0.f, ps1 = 0.f;
#pragma unroll
            for (int j = 0; j < 8; j++) {
                s[j][0] = __expf(s[j][0] - mn0);
                s[j][1] = __expf(s[j][1] - mn0);
                s[j][2] = __expf(s[j][2] - mn1);
                s[j][3] = __expf(s[j][3] - mn1);
                ps0 += s[j][0] + s[j][1];
                ps1 += s[j][2] + s[j][3];
            }
            ps0 += __shfl_xor_sync(0xffffffffu, ps0, 1);
            ps0 += __shfl_xor_sync(0xffffffffu, ps0, 2);
            ps1 += __shfl_xor_sync(0xffffffffu, ps1, 1);
            ps1 += __shfl_xor_sync(0xffffffffu, ps1, 2);
            lrow0 = lrow0 * al0 + ps0;
            lrow1 = lrow1 * al1 + ps1;
#pragma unroll
            for (int j = 0; j < 8; j++) {
                oacc[j][0] *= al0; oacc[j][1] *= al0;
                oacc[j][2] *= al1; oacc[j][3] *= al1;
            }

            // ---- O += P_half V_half (3-pass hi/lo, P from S regs) ----
#pragma unroll
            for (int kt = 0; kt < 4; kt++) {
                const uint32_t ah0 = packbf(s[2 * kt][0],     s[2 * kt][1]);
                const uint32_t ah1 = packbf(s[2 * kt][2],     s[2 * kt][3]);
                const uint32_t ah2 = packbf(s[2 * kt + 1][0], s[2 * kt + 1][1]);
                const uint32_t ah3 = packbf(s[2 * kt + 1][2], s[2 * kt + 1][3]);
                const uint32_t al0_ = packlo(s[2 * kt][0],     s[2 * kt][1]);
                const uint32_t al1_ = packlo(s[2 * kt][2],     s[2 * kt][3]);
                const uint32_t al2_ = packlo(s[2 * kt + 1][0], s[2 * kt + 1][1]);
                const uint32_t al3_ = packlo(s[2 * kt + 1][2], s[2 * kt + 1][3]);
                const int gkt = half * 4 + kt;   // global 16-m-step in chunk
#pragma unroll
                for (int vg = 0; vg < 4; vg++) {
                    uint32_t vh4[4], vl4[4];
                    const int row = vg * 16 + frow;
                    const uint32_t off = row * 256 + ((((gkt << 1) + fchk) ^ (row & 15)) << 4);
                    ldm4(vh4[0], vh4[1], vh4[2], vh4[3], sVh + off);
                    ldm4(vl4[0], vl4[1], vl4[2], vl4[3], sVl + off);
#pragma unroll
                    for (int o = 0; o < 2; o++) {
                        float* a = oacc[vg * 2 + o];
                        mma_bf16(a[0], a[1], a[2], a[3], ah0, ah1, ah2, ah3,
                                 vh4[o], vh4[o + 2]);
                        mma_bf16(a[0], a[1], a[2], a[3], ah0, ah1, ah2, ah3,
                                 vl4[o], vl4[o + 2]);
                        mma_bf16(a[0], a[1], a[2], a[3], al0_, al1_, al2_, al3_,
                                 vh4[o], vh4[o + 2]);
                    }
                }
            }
        }
    }

    // ---- epilogue: normalize + write bf16 hi/lo at [b][n][h*64+dk] ----
    const float inv0 = 1.f / lrow0;
    const float inv1 = 1.f / lrow1;
    const int g = lid >> 2, t = lid & 3;
    const long r0 = n0 + wid * 16 + g;
    const long r1 = r0 + 8;
#pragma unroll
    for (int j = 0; j < 8; j++) {
        const int cc = h * 64 + j * 8 + t * 2;
        const float v00 = oacc[j][0] * inv0, v01 = oacc[j][1] * inv0;
        const float v10 = oacc[j][2] * inv1, v11 = oacc[j][3] * inv1;
        const long o0 = ((long)b * NN + r0) * DIM + cc;
        const long o1 = ((long)b * NN + r1) * DIM + cc;
        *(uint32_t*)(Oh + o0) = packbf(v00, v01);
        *(uint32_t*)(Oh + o1) = packbf(v10, v11);
        *(uint32_t*)(Ol + o0) = packlo(v00, v01);
        *(uint32_t*)(Ol + o1) = packlo(v10, v11);
    }
}

// ---------------------------------------------------------------------------
// Host launch
// ---------------------------------------------------------------------------
extern "C" void kernel_launch(void* const* d_in, const int* in_sizes, int n_in,
                              void* d_out, int out_size)
{
    const float* motion = (const float*)d_in[0];
    const float* Wq = (const float*)d_in[1];
    const float* bq = (const float*)d_in[2];
    const float* Wk = (const float*)d_in[3];
    const float* bk = (const float*)d_in[4];
    const float* Wv = (const float*)d_in[5];
    const float* bv = (const float*)d_in[6];
    const float* Wm = (const float*)d_in[7];
    const float* bm = (const float*)d_in[8];
    const float* Wp1 = (const float*)d_in[9];
    const float* bp1 = (const float*)d_in[10];
    const float* bng = (const float*)d_in[11];
    const float* bnb = (const float*)d_in[12];
    const float* bnm = (const float*)d_in[13];
    const float* bnv = (const float*)d_in[14];
    const float* Wp2 = (const float*)d_in[15];
    const float* bp2 = (const float*)d_in[16];
    float* out = (float*)d_out;

    float *Qb, *Kb, *Vb, *MRG, *H1, *X0, *X1;
    cudaGetSymbolAddress((void**)&Qb,  g_Q);
    cudaGetSymbolAddress((void**)&Kb,  g_K);
    cudaGetSymbolAddress((void**)&Vb,  g_V);
    cudaGetSymbolAddress((void**)&MRG, g_MRG);
    cudaGetSymbolAddress((void**)&H1,  g_H1);
    cudaGetSymbolAddress((void**)&X0,  g_X0);
    cudaGetSymbolAddress((void**)&X1,  g_X1);

    __nv_bfloat16 *WqH, *WqL, *WkH, *WkL, *WvH, *WvL, *WmH, *WmL, *W1H, *W1L, *W2H, *W2L;
    __nv_bfloat16 *XTh, *XTl, *MTh, *MTl, *HTh, *HTl;
    __nv_bfloat16 *QTh, *QTl, *KTh, *KTl, *VTh, *VTl, *OTh, *OTl;
    cudaGetSymbolAddress((void**)&WqH, g_WqH); cudaGetSymbolAddress((void**)&WqL, g_WqL);
    cudaGetSymbolAddress((void**)&WkH, g_WkH); cudaGetSymbolAddress((void**)&WkL, g_WkL);
    cudaGetSymbolAddress((void**)&WvH, g_WvH); cudaGetSymbolAddress((void**)&WvL, g_WvL);
    cudaGetSymbolAddress((void**)&WmH, g_WmH); cudaGetSymbolAddress((void**)&WmL, g_WmL);
    cudaGetSymbolAddress((void**)&W1H, g_W1H); cudaGetSymbolAddress((void**)&W1L, g_W1L);
    cudaGetSymbolAddress((void**)&W2H, g_W2H); cudaGetSymbolAddress((void**)&W2L, g_W2L);
    cudaGetSymbolAddress((void**)&XTh, g_XTh); cudaGetSymbolAddress((void**)&XTl, g_XTl);
    cudaGetSymbolAddress((void**)&MTh, g_MTh); cudaGetSymbolAddress((void**)&MTl, g_MTl);
    cudaGetSymbolAddress((void**)&HTh, g_HTh); cudaGetSymbolAddress((void**)&HTl, g_HTl);
    cudaGetSymbolAddress((void**)&QTh, g_QTh); cudaGetSymbolAddress((void**)&QTl, g_QTl);
    cudaGetSymbolAddress((void**)&KTh, g_KTh); cudaGetSymbolAddress((void**)&KTl, g_KTl);
    cudaGetSymbolAddress((void**)&VTh, g_VTh); cudaGetSymbolAddress((void**)&VTl, g_VTl);
    cudaGetSymbolAddress((void**)&OTh, g_OTh); cudaGetSymbolAddress((void**)&OTl, g_OTl);

    cudaFuncSetAttribute(mma_gemm, cudaFuncAttributeMaxDynamicSharedMemorySize, MG_SMEM);
    cudaFuncSetAttribute(flash_k, cudaFuncAttributeMaxDynamicSharedMemorySize, FL_SMEM);

    // weight conversions (all layers)
    const int nDD  = LAYERS * DIM * DIM;
    const int n2D2 = LAYERS * TWOD * TWOD;
    const int nD2  = LAYERS * DIM * TWOD;
    cvt_w<<<nDD / 1024, 256>>>(Wq, WqH, WqL, nDD);
    cvt_w<<<nDD / 1024, 256>>>(Wk, WkH, WkL, nDD);
    cvt_w<<<nDD / 1024, 256>>>(Wv, WvH, WvL, nDD);
    cvt_wm<<<nDD / 1024, 256>>>(Wm, WmH, WmL, nDD);   // column-permuted for head-blocked O
    cvt_w<<<n2D2 / 1024, 256>>>(Wp1, W1H, W1L, n2D2);
    cvt_w<<<nD2 / 1024, 256>>>(Wp2, W2H, W2L, nD2);

    const dim3 gT1(NN / 32, DIM / 32, BATCH);
    const dim3 gT2(NN / 32, TWOD / 32, BATCH);
    const dim3 gQK(NN / 32, DK / 32, BATCH * HEADS);
    const dim3 blkT(32, 8);
    const dim3 gG1(32, DIM / 128);
    const dim3 gG2(32, TWOD / 128);
    const dim3 gFl(NN / 128, BATCH * HEADS);
    const long cbs1 = (long)DIM * NN;
    const long cbs2 = (long)TWOD * NN;
    const int nBDN = BATCH * DIM * NN;

    for (int l = 0; l < LAYERS; l++) {
        const float* xin = (l == 0) ? motion : ((l & 1) ? X1 : X0);
        float* xout = (l == 3) ? out : ((l & 1) ? X0 : X1);
        const long oDD = (long)l * DIM * DIM;
        const long o2D2 = (long)l * TWOD * TWOD;
        const long oD2 = (long)l * DIM * TWOD;

        // x -> transposed bf16 hi/lo
        tcvt<<<gT1, blkT>>>(xin, XTh, XTl, DIM);

        // Q, K, V projections (fp32 outputs)
        mma_gemm<<<gG1, 256, MG_SMEM>>>(WqH + oDD, WqL + oDD, DIM,
                                        XTh, XTl, DIM, 32, XTh, XTl, DIM, 32,
                                        bq + l * DIM, nullptr, nullptr, nullptr, nullptr,
                                        nullptr, Qb, cbs1);
        mma_gemm<<<gG1, 256, MG_SMEM>>>(WkH + oDD, WkL + oDD, DIM,
                                        XTh, XTl, DIM, 32, XTh, XTl, DIM, 32,
                                        bk + l * DIM, nullptr, nullptr, nullptr, nullptr,
                                        nullptr, Kb, cbs1);
        mma_gemm<<<gG1, 256, MG_SMEM>>>(WvH + oDD, WvL + oDD, DIM,
                                        XTh, XTl, DIM, 32, XTh, XTl, DIM, 32,
                                        bv + l * DIM, nullptr, nullptr, nullptr, nullptr,
                                        nullptr, Vb, cbs1);

        // attention operand conversions
        qk_tcvt<<<gQK, blkT>>>(Qb, QTh, QTl, 0.125f);   // 1/sqrt(64) folded into Q
        qk_tcvt<<<gQK, blkT>>>(Kb, KTh, KTl, 1.0f);
        cvt_w<<<nBDN / 1024, 256>>>(Vb, VTh, VTl, nBDN);

        // fused flash attention -> OTh/OTl (head-blocked bf16 hi/lo)
        flash_k<<<gFl, 256, FL_SMEM>>>(QTh, QTl, KTh, KTl, VTh, VTl, OTh, OTl);

        // merge projection (permuted weights, B = flash output directly)
        mma_gemm<<<gG1, 256, MG_SMEM>>>(WmH + oDD, WmL + oDD, DIM,
                                        OTh, OTl, DIM, 32, OTh, OTl, DIM, 32,
                                        bm + l * DIM, nullptr, nullptr, nullptr, nullptr,
                                        nullptr, MRG, cbs1);

        // p1: Wp1 @ concat(merged, x) + bias -> BN -> ReLU
        tcvt<<<gT1, blkT>>>(MRG, MTh, MTl, DIM);
        mma_gemm<<<gG2, 256, MG_SMEM>>>(W1H + o2D2, W1L + o2D2, TWOD,
                                        MTh, MTl, DIM, 32, XTh, XTl, DIM, 64,
                                        bp1 + l * TWOD,
                                        bng + l * TWOD, bnb + l * TWOD,
                                        bnm + l * TWOD, bnv + l * TWOD,
                                        nullptr, H1, cbs2);

        // p2: Wp2 @ h + bias + residual
        tcvt<<<gT2, blkT>>>(H1, HTh, HTl, TWOD);
        mma_gemm<<<gG1, 256, MG_SMEM>>>(W2H + oD2, W2L + oD2, TWOD,
                                        HTh, HTl, TWOD, 64, HTh, HTl, TWOD, 64,
                                        bp2 + l * DIM, nullptr, nullptr, nullptr, nullptr,
                                        xin, xout, cbs1);
    }
}

// round 15
// speedup vs baseline: 2.8569x; 1.0081x over previous
#include <cuda_runtime.h>
#include <cuda_bf16.h>
#include <cstdint>

#define BATCH 4
#define DIM   1024
#define HEADS 16
#define DK    64
#define NN    1024
#define LAYERS 4
#define TWOD  2048
#define BN_EPS 1e-5f

// ---------------------------------------------------------------------------
// Scratch (device globals — no allocation allowed)
// ---------------------------------------------------------------------------
__device__ float g_MRG[BATCH * DIM * NN];
__device__ float g_H1 [BATCH * TWOD * NN];
__device__ float g_X0 [BATCH * DIM * NN];
__device__ float g_X1 [BATCH * DIM * NN];

// bf16 hi/lo weight copies (converted each call)
__device__ __nv_bfloat16 g_WqkvH[LAYERS * 3 * DIM * DIM], g_WqkvL[LAYERS * 3 * DIM * DIM];
__device__ float         g_bqkv [LAYERS * 3 * DIM];
__device__ __nv_bfloat16 g_WmH[LAYERS * DIM * DIM],  g_WmL[LAYERS * DIM * DIM]; // col-permuted
__device__ __nv_bfloat16 g_W1H[LAYERS * TWOD * TWOD], g_W1L[LAYERS * TWOD * TWOD];
__device__ __nv_bfloat16 g_W2H[LAYERS * DIM * TWOD],  g_W2L[LAYERS * DIM * TWOD];

// bf16 hi/lo transposed activations: [b][n][k]
__device__ __nv_bfloat16 g_XTh[BATCH * NN * DIM],  g_XTl[BATCH * NN * DIM];
__device__ __nv_bfloat16 g_MTh[BATCH * NN * DIM],  g_MTl[BATCH * NN * DIM];
__device__ __nv_bfloat16 g_HTh[BATCH * NN * TWOD], g_HTl[BATCH * NN * TWOD];
// stacked QKV, channel-major bf16 hi/lo: [b][3*DIM][n]  (Q rows pre-scaled 1/8)
__device__ __nv_bfloat16 g_QKVh[BATCH * 3 * DIM * NN], g_QKVl[BATCH * 3 * DIM * NN];
// flash output, head-blocked channels: [b][n][h*64+dk]
__device__ __nv_bfloat16 g_OTh[BATCH * NN * DIM], g_OTl[BATCH * NN * DIM];

// ---------------------------------------------------------------------------
// PTX helpers (base sm_80+ ISA only — no tcgen05 on this build target)
// ---------------------------------------------------------------------------
__device__ __forceinline__ uint32_t smem_u32(const void* p) {
    return (uint32_t)__cvta_generic_to_shared(p);
}
__device__ __forceinline__ void cpa16(uint32_t dst, const void* src) {
    asm volatile("cp.async.cg.shared.global [%0], [%1], 16;"
                 :: "r"(dst), "l"(__cvta_generic_to_global(src)) : "memory");
}
#define CP_COMMIT() asm volatile("cp.async.commit_group;" ::: "memory")
#define CP_WAIT1()  asm volatile("cp.async.wait_group 1;" ::: "memory")
#define CP_WAIT0()  asm volatile("cp.async.wait_group 0;" ::: "memory")

__device__ __forceinline__ void ldm4(uint32_t& r0, uint32_t& r1, uint32_t& r2,
                                     uint32_t& r3, uint32_t addr) {
    asm volatile("ldmatrix.sync.aligned.m8n8.x4.shared.b16 {%0,%1,%2,%3}, [%4];"
                 : "=r"(r0), "=r"(r1), "=r"(r2), "=r"(r3) : "r"(addr));
}
// transposed variant: loads 4 8x8 b16 tiles transposed (physical [k][m] -> logical [m][k])
__device__ __forceinline__ void ldm4t(uint32_t& r0, uint32_t& r1, uint32_t& r2,
                                      uint32_t& r3, uint32_t addr) {
    asm volatile("ldmatrix.sync.aligned.m8n8.x4.trans.shared.b16 {%0,%1,%2,%3}, [%4];"
                 : "=r"(r0), "=r"(r1), "=r"(r2), "=r"(r3) : "r"(addr));
}
__device__ __forceinline__ void mma_bf16(float& c0, float& c1, float& c2, float& c3,
                                         uint32_t a0, uint32_t a1, uint32_t a2,
                                         uint32_t a3, uint32_t b0, uint32_t b1) {
    asm volatile("mma.sync.aligned.m16n8k16.row.col.f32.bf16.bf16.f32 "
                 "{%0,%1,%2,%3}, {%4,%5,%6,%7}, {%8,%9}, {%0,%1,%2,%3};"
                 : "+f"(c0), "+f"(c1), "+f"(c2), "+f"(c3)
                 : "r"(a0), "r"(a1), "r"(a2), "r"(a3), "r"(b0), "r"(b1));
}
// pack two f32 -> bf16x2 {lo, hi}
__device__ __forceinline__ uint32_t packbf(float lo, float hi) {
    uint32_t r;
    asm("cvt.rn.bf16x2.f32 %0, %1, %2;" : "=r"(r) : "f"(hi), "f"(lo));
    return r;
}
__device__ __forceinline__ uint32_t packlo(float lo, float hi) {
    float rl = lo - __bfloat162float(__float2bfloat16(lo));
    float rh = hi - __bfloat162float(__float2bfloat16(hi));
    return packbf(rl, rh);
}

// ---------------------------------------------------------------------------
// Conversion: fp32 -> bf16 hi/lo split
// ---------------------------------------------------------------------------
__device__ __forceinline__ void split2(float x, __nv_bfloat16& h, __nv_bfloat16& l) {
    h = __float2bfloat16(x);
    l = __float2bfloat16(x - __bfloat162float(h));
}

__global__ __launch_bounds__(256)
void cvt_w(const float* __restrict__ w, __nv_bfloat16* __restrict__ hi,
           __nv_bfloat16* __restrict__ lo, int n)
{
    int i = (blockIdx.x * 256 + threadIdx.x) * 4;
    if (i >= n) return;
    float4 v = *(const float4*)(w + i);
    split2(v.x, hi[i + 0], lo[i + 0]);
    split2(v.y, hi[i + 1], lo[i + 1]);
    split2(v.z, hi[i + 2], lo[i + 2]);
    split2(v.w, hi[i + 3], lo[i + 3]);
}

// stack Wq/Wk/Wv per layer: out[l][sec][DD]
__global__ __launch_bounds__(256)
void cvt_qkv(const float* __restrict__ Wq, const float* __restrict__ Wk,
             const float* __restrict__ Wv,
             __nv_bfloat16* __restrict__ hi, __nv_bfloat16* __restrict__ lo)
{
    const int DD = DIM * DIM;
    int i = (blockIdx.x * 256 + threadIdx.x) * 4;
    int l = i / (3 * DD);
    int rem = i - l * (3 * DD);
    int sec = rem / DD;
    int off = rem - sec * DD;
    const float* src = (sec == 0 ? Wq : (sec == 1 ? Wk : Wv)) + l * DD + off;
    float4 v = *(const float4*)src;
    split2(v.x, hi[i + 0], lo[i + 0]);
    split2(v.y, hi[i + 1], lo[i + 1]);
    split2(v.z, hi[i + 2], lo[i + 2]);
    split2(v.w, hi[i + 3], lo[i + 3]);
}

__global__ __launch_bounds__(256)
void cvt_bias(const float* __restrict__ bq, const float* __restrict__ bk,
              const float* __restrict__ bv, float* __restrict__ out)
{
    int i = blockIdx.x * 256 + threadIdx.x;      // LAYERS*3*DIM
    int l = i / (3 * DIM);
    int rem = i - l * (3 * DIM);
    int sec = rem / DIM;
    int off = rem - sec * DIM;
    const float* s = (sec == 0 ? bq : (sec == 1 ? bk : bv));
    out[i] = s[l * DIM + off];
}

// merge weight: permute input channels c = dk*16+h -> c' = h*64+dk
__global__ __launch_bounds__(256)
void cvt_wm(const float* __restrict__ w, __nv_bfloat16* __restrict__ hi,
            __nv_bfloat16* __restrict__ lo, int n)
{
    int i = (blockIdx.x * 256 + threadIdx.x) * 4;
    if (i >= n) return;
    int rowbase = i & ~1023;
#pragma unroll
    for (int u = 0; u < 4; u++) {
        int jp = (i + u) & 1023;              // c' = h*64+dk
        int j = ((jp & 63) << 4) | (jp >> 6); // c  = dk*16+h
        split2(w[rowbase + j], hi[i + u], lo[i + u]);
    }
}

// Transpose + convert: in [b][K][NN] fp32 -> out [b][NN][K] bf16 hi/lo
__global__ __launch_bounds__(256)
void tcvt(const float* __restrict__ in, __nv_bfloat16* __restrict__ hi,
          __nv_bfloat16* __restrict__ lo, int K)
{
    __shared__ float t[32][33];
    const int b = blockIdx.z;
    const float* ip = in + (long)b * K * NN;
    __nv_bfloat16* hp = hi + (long)b * NN * K;
    __nv_bfloat16* lp = lo + (long)b * NN * K;
    const int n0 = blockIdx.x * 32, k0 = blockIdx.y * 32;
    const int tx = threadIdx.x, ty = threadIdx.y;  // (32, 8)
#pragma unroll
    for (int r = 0; r < 4; r++) {
        int kk = ty + r * 8;
        t[kk][tx] = ip[(long)(k0 + kk) * NN + n0 + tx];
    }
    __syncthreads();
#pragma unroll
    for (int r = 0; r < 4; r++) {
        int nn = ty + r * 8;
        float v = t[tx][nn];
        long o = (long)(n0 + nn) * K + k0 + tx;
        split2(v, hp[o], lp[o]);
    }
}

// ---------------------------------------------------------------------------
// HMMA GEMM: C[b,i,n0+j] = sum_k A[i,k]*B[b,j,k]
// fp32 out (C/res) OR bf16 hi/lo channel-major out (obh/obl, row-scale for QKV)
// ---------------------------------------------------------------------------
#define MG_SMEM (2 * 32768)

__global__ __launch_bounds__(256, 1)
void mma_gemm(const __nv_bfloat16* __restrict__ Ah, const __nv_bfloat16* __restrict__ Al,
              int lda,
              const __nv_bfloat16* __restrict__ B1h, const __nv_bfloat16* __restrict__ B1l,
              int ldb1, int nc1,
              const __nv_bfloat16* __restrict__ B2h, const __nv_bfloat16* __restrict__ B2l,
              int ldb2, int nctot,
              const float* __restrict__ bias,
              const float* __restrict__ bng, const float* __restrict__ bnb,
              const float* __restrict__ bnm, const float* __restrict__ bnv,
              const float* __restrict__ res, float* __restrict__ C, long cbs,
              __nv_bfloat16* __restrict__ obh, __nv_bfloat16* __restrict__ obl,
              int obM, int scaleRows)
{
    extern __shared__ __align__(128) char dsm[];
    const uint32_t smem_base = smem_u32(dsm);

    const int tid = threadIdx.x;
    const int wid = tid >> 5, lid = tid & 31;
    const int warp_m = wid & 1;
    const int warp_n = wid >> 1;
    const int j0 = blockIdx.x * 128;
    const int b  = j0 >> 10;
    const int n0 = j0 & 1023;
    const int i0 = blockIdx.y * 128;

    const __nv_bfloat16* b1h = B1h + (long)b * NN * ldb1;
    const __nv_bfloat16* b1l = B1l + (long)b * NN * ldb1;
    const __nv_bfloat16* b2h = B2h + (long)b * NN * ldb2;
    const __nv_bfloat16* b2l = B2l + (long)b * NN * ldb2;

    const int frow = ((lid >> 3) & 1) * 8 + (lid & 7);
    const int fchk = lid >> 4;
    uint32_t offA[4][2], offB[2][2];
#pragma unroll
    for (int mt = 0; mt < 4; mt++) {
        const int row = warp_m * 64 + mt * 16 + frow;
#pragma unroll
        for (int s16 = 0; s16 < 2; s16++) {
            const int ch = s16 * 2 + fchk;
            offA[mt][s16] = row * 64 + ((ch ^ ((row >> 1) & 3)) << 4);
        }
    }
#pragma unroll
    for (int np = 0; np < 2; np++) {
        const int row = warp_n * 32 + np * 16 + frow;
#pragma unroll
        for (int s16 = 0; s16 < 2; s16++) {
            const int ch = s16 * 2 + fchk;
            offB[np][s16] = row * 64 + ((ch ^ ((row >> 1) & 3)) << 4);
        }
    }

    float acc[4][4][4];
#pragma unroll
    for (int mt = 0; mt < 4; mt++)
#pragma unroll
        for (int nt = 0; nt < 4; nt++)
#pragma unroll
            for (int q = 0; q < 4; q++) acc[mt][nt][q] = 0.f;

    auto load_stage = [&](int c, int s) {
        const uint32_t sb = smem_base + s * 32768;
        const __nv_bfloat16 *pbh, *pbl;
        long kb;
        int ldb;
        if (c < nc1) { pbh = b1h; pbl = b1l; ldb = ldb1; kb = (long)c * 32; }
        else         { pbh = b2h; pbl = b2l; ldb = ldb2; kb = (long)(c - nc1) * 32; }
#pragma unroll
        for (int it = 0; it < 2; it++) {
            const int si = it * 256 + tid;
            const int row = si >> 2, ch = si & 3;
            const uint32_t dsw = row * 64 + ((ch ^ ((row >> 1) & 3)) << 4);
            cpa16(sb + dsw,          Ah + (long)(i0 + row) * lda + (long)c * 32 + ch * 8);
            cpa16(sb + 8192 + dsw,   Al + (long)(i0 + row) * lda + (long)c * 32 + ch * 8);
            cpa16(sb + 16384 + dsw,  pbh + (long)(n0 + row) * ldb + kb + ch * 8);
            cpa16(sb + 24576 + dsw,  pbl + (long)(n0 + row) * ldb + kb + ch * 8);
        }
    };

    load_stage(0, 0);
    CP_COMMIT();

    for (int c = 0; c < nctot; c++) {
        if (c + 1 < nctot) {
            load_stage(c + 1, (c + 1) & 1);
            CP_COMMIT();
            CP_WAIT1();
        } else {
            CP_WAIT0();
        }
        __syncthreads();

        const uint32_t sb  = smem_base + (c & 1) * 32768;
        const uint32_t sAh = sb, sAl = sb + 8192, sBh = sb + 16384, sBl = sb + 24576;
#pragma unroll
        for (int s16 = 0; s16 < 2; s16++) {
            uint32_t ah[4][4], al_[4][4], bh[2][4], bl[2][4];
#pragma unroll
            for (int mt = 0; mt < 4; mt++) {
                ldm4(ah[mt][0], ah[mt][1], ah[mt][2], ah[mt][3], sAh + offA[mt][s16]);
                ldm4(al_[mt][0], al_[mt][1], al_[mt][2], al_[mt][3], sAl + offA[mt][s16]);
            }
#pragma unroll
            for (int np = 0; np < 2; np++) {
                ldm4(bh[np][0], bh[np][1], bh[np][2], bh[np][3], sBh + offB[np][s16]);
                ldm4(bl[np][0], bl[np][1], bl[np][2], bl[np][3], sBl + offB[np][s16]);
            }
#pragma unroll
            for (int mt = 0; mt < 4; mt++) {
#pragma unroll
                for (int nt = 0; nt < 4; nt++) {
                    const int np = nt >> 1, o = nt & 1;
                    float* a = acc[mt][nt];
                    mma_bf16(a[0], a[1], a[2], a[3],
                             ah[mt][0], ah[mt][1], ah[mt][2], ah[mt][3],
                             bh[np][o], bh[np][o + 2]);
                    mma_bf16(a[0], a[1], a[2], a[3],
                             ah[mt][0], ah[mt][1], ah[mt][2], ah[mt][3],
                             bl[np][o], bl[np][o + 2]);
                    mma_bf16(a[0], a[1], a[2], a[3],
                             al_[mt][0], al_[mt][1], al_[mt][2], al_[mt][3],
                             bh[np][o], bh[np][o + 2]);
                }
            }
        }
        __syncthreads();
    }

    const int g = lid >> 2, t = lid & 3;
    if (obh) {
        // bf16 hi/lo channel-major output with per-row scale (QKV path)
#pragma unroll
        for (int mt = 0; mt < 4; mt++) {
#pragma unroll
            for (int half = 0; half < 2; half++) {
                const int r = i0 + warp_m * 64 + mt * 16 + g + half * 8;
                const float bi = bias[r];
                const float sc = (r < scaleRows) ? 0.125f : 1.0f;
                const long ob = ((long)b * obM + r) * NN + n0 + warp_n * 32 + t * 2;
                __nv_bfloat16* oh = obh + ob;
                __nv_bfloat16* ol = obl + ob;
#pragma unroll
                for (int nt = 0; nt < 4; nt++) {
                    const float v0 = (acc[mt][nt][half * 2 + 0] + bi) * sc;
                    const float v1 = (acc[mt][nt][half * 2 + 1] + bi) * sc;
                    *(uint32_t*)(oh + nt * 8) = packbf(v0, v1);
                    *(uint32_t*)(ol + nt * 8) = packlo(v0, v1);
                }
            }
        }
        return;
    }
    const bool bn = (bng != nullptr);
#pragma unroll
    for (int mt = 0; mt < 4; mt++) {
#pragma unroll
        for (int half = 0; half < 2; half++) {
            const int r = i0 + warp_m * 64 + mt * 16 + g + half * 8;
            const float bi = bias[r];
            float sa = 0.f, sbb = 0.f;
            if (bn) {
                const float inv = rsqrtf(bnv[r] + BN_EPS);
                sa = bng[r] * inv;
                sbb = bnb[r] - sa * bnm[r];
            }
            float* cp_ = C + (long)b * cbs + (long)r * NN + n0 + warp_n * 32 + t * 2;
            const float* rp = res ? res + (long)b * ((long)DIM * NN) + (long)r * NN
                                        + n0 + warp_n * 32 + t * 2
                                  : nullptr;
#pragma unroll
            for (int nt = 0; nt < 4; nt++) {
                float v0 = acc[mt][nt][half * 2 + 0] + bi;
                float v1 = acc[mt][nt][half * 2 + 1] + bi;
                if (bn) {
                    v0 = fmaxf(fmaf(sa, v0, sbb), 0.f);
                    v1 = fmaxf(fmaf(sa, v1, sbb), 0.f);
                }
                if (rp) {
                    float2 rr = *(const float2*)(rp + nt * 8);
                    v0 += rr.x; v1 += rr.y;
                }
                *(float2*)(cp_ + nt * 8) = make_float2(v0, v1);
            }
        }
    }
}

// ---------------------------------------------------------------------------
// Flash attention (HMMA, hi/lo). Grid (NN/128, B*H), 256 threads.
// All operands channel-major [dk64][n/m 128] (rows 256B, swizzle ch^(row&15)),
// Q/K fragments via ldmatrix.trans; V via non-trans (as before).
// Q pre-scaled by 1/8 in the QKV GEMM epilogue.
// Output: [b][n][h*64+dk] bf16 hi/lo.
// ---------------------------------------------------------------------------
#define FL_SMEM (6 * 16384)

__global__ __launch_bounds__(256, 1)
void flash_k(const __nv_bfloat16* __restrict__ QKVh, const __nv_bfloat16* __restrict__ QKVl,
             __nv_bfloat16* __restrict__ Oh, __nv_bfloat16* __restrict__ Ol)
{
    extern __shared__ __align__(128) char fsm[];
    const uint32_t base = smem_u32(fsm);
    const int tid = threadIdx.x, wid = tid >> 5, lid = tid & 31;
    const int n0 = blockIdx.x * 128;
    const int bh = blockIdx.y;
    const int b = bh >> 4, h = bh & 15;

    const uint32_t sQh = base,          sQl = base + 16384;
    const uint32_t sKh = base + 32768,  sKl = base + 49152;
    const uint32_t sVh = base + 65536,  sVl = base + 81920;

    // section bases in stacked channel-major QKV (rows c = dk*16 + h)
    const long secQ = (long)b * 3 * DIM * NN;
    const long secK = secQ + (long)DIM * NN;
    const long secV = secQ + 2 * (long)DIM * NN;

    // ---- load Q tile [dk64][n128] ----
#pragma unroll
    for (int it = 0; it < 4; it++) {
        const int si = it * 256 + tid;
        const int row = si >> 4, ch = si & 15;
        const uint32_t d = row * 256 + ((ch ^ (row & 15)) << 4);
        const long src = secQ + (long)(row * 16 + h) * NN + n0 + ch * 8;
        cpa16(sQh + d, QKVh + src);
        cpa16(sQl + d, QKVl + src);
    }
    CP_COMMIT(); CP_WAIT0(); __syncthreads();

    const int frow = ((lid >> 3) & 1) * 8 + (lid & 7);
    const int fchk = lid >> 4;
    // trans-ldmatrix lane constants: lk = physical k-row within 16-block,
    // lmo = +8 column-window selector
    const int lk  = ((lid >> 4) << 3) + (lid & 7);   // 0..15
    const int lmo = (lid >> 3) & 1;

    // Q fragments (loop invariant): 4 k-steps, A-frag via trans from [dk][n]
    uint32_t qh[4][4], ql[4][4];
    {
        const int mb = (wid * 16) >> 3;   // this warp's query-row chunk base
#pragma unroll
        for (int ks = 0; ks < 4; ks++) {
            const uint32_t a = (ks * 16 + lk) * 256 + ((((mb + lmo)) ^ lk) << 4);
            ldm4t(qh[ks][0], qh[ks][1], qh[ks][2], qh[ks][3], sQh + a);
            ldm4t(ql[ks][0], ql[ks][1], ql[ks][2], ql[ks][3], sQl + a);
        }
    }

    float oacc[8][4];
#pragma unroll
    for (int j = 0; j < 8; j++)
#pragma unroll
        for (int q = 0; q < 4; q++) oacc[j][q] = 0.f;
    float mrow0 = -1e30f, mrow1 = -1e30f;
    float lrow0 = 0.f, lrow1 = 0.f;

#pragma unroll 1
    for (int c0 = 0; c0 < NN; c0 += 128) {
        __syncthreads();   // previous chunk's smem reads done
        // ---- load K and V chunks [dk64][m128] ----
#pragma unroll
        for (int it = 0; it < 4; it++) {
            const int si = it * 256 + tid;
            const int row = si >> 4, ch = si & 15;
            const uint32_t d = row * 256 + ((ch ^ (row & 15)) << 4);
            const long srcK = secK + (long)(row * 16 + h) * NN + c0 + ch * 8;
            const long srcV = secV + (long)(row * 16 + h) * NN + c0 + ch * 8;
            cpa16(sKh + d, QKVh + srcK);
            cpa16(sKl + d, QKVl + srcK);
            cpa16(sVh + d, QKVh + srcV);
            cpa16(sVl + d, QKVl + srcV);
        }
        CP_COMMIT(); CP_WAIT0(); __syncthreads();

#pragma unroll 1
        for (int half = 0; half < 2; half++) {
            // ---- S_half = Q K^T over 64 m-cols (3-pass hi/lo) ----
            float s[8][4];
#pragma unroll
            for (int j = 0; j < 8; j++)
#pragma unroll
                for (int q = 0; q < 4; q++) s[j][q] = 0.f;

#pragma unroll
            for (int g8 = 0; g8 < 4; g8++) {
                uint32_t kh4[4][4], kl4[4][4];
                const int mb = (half * 64 + g8 * 16) >> 3;
#pragma unroll
                for (int ks = 0; ks < 4; ks++) {
                    const uint32_t a = (ks * 16 + lk) * 256 + (((mb + lmo) ^ lk) << 4);
                    ldm4t(kh4[ks][0], kh4[ks][1], kh4[ks][2], kh4[ks][3], sKh + a);
                    ldm4t(kl4[ks][0], kl4[ks][1], kl4[ks][2], kl4[ks][3], sKl + a);
                }
#pragma unroll
                for (int o = 0; o < 2; o++) {
                    float* a = s[g8 * 2 + o];
#pragma unroll
                    for (int ks = 0; ks < 4; ks++) {
                        mma_bf16(a[0], a[1], a[2], a[3],
                                 qh[ks][0], qh[ks][1], qh[ks][2], qh[ks][3],
                                 kh4[ks][o], kh4[ks][o + 2]);
                        mma_bf16(a[0], a[1], a[2], a[3],
                                 qh[ks][0], qh[ks][1], qh[ks][2], qh[ks][3],
                                 kl4[ks][o], kl4[ks][o + 2]);
                        mma_bf16(a[0], a[1], a[2], a[3],
                                 ql[ks][0], ql[ks][1], ql[ks][2], ql[ks][3],
                                 kh4[ks][o], kh4[ks][o + 2]);
                    }
                }
            }

            // ---- online softmax update (rows: pair 0 = g, pair 1 = g+8) ----
            float cm0 = -1e30f, cm1 = -1e30f;
#pragma unroll
            for (int j = 0; j < 8; j++) {
                cm0 = fmaxf(cm0, fmaxf(s[j][0], s[j][1]));
                cm1 = fmaxf(cm1, fmaxf(s[j][2], s[j][3]));
            }
            cm0 = fmaxf(cm0, __shfl_xor_sync(0xffffffffu, cm0, 1));
            cm0 = fmaxf(cm0, __shfl_xor_sync(0xffffffffu, cm0, 2));
            cm1 = fmaxf(cm1, __shfl_xor_sync(0xffffffffu, cm1, 1));
            cm1 = fmaxf(cm1, __shfl_xor_sync(0xffffffffu, cm1, 2));
            const float mn0 = fmaxf(mrow0, cm0);
            const float mn1 = fmaxf(mrow1, cm1);
            const float al0 = __expf(mrow0 - mn0);
            const float al1 = __expf(mrow1 - mn1);
            mrow0 = mn0; mrow1 = mn1;

            float ps0 = 0.f, ps1 = 0.f;
#pragma unroll
            for (int j = 0; j < 8; j++) {
                s[j][0] = __expf(s[j][0] - mn0);
                s[j][1] = __expf(s[j][1] - mn0);
                s[j][2] = __expf(s[j][2] - mn1);
                s[j][3] = __expf(s[j][3] - mn1);
                ps0 += s[j][0] + s[j][1];
                ps1 += s[j][2] + s[j][3];
            }
            ps0 += __shfl_xor_sync(0xffffffffu, ps0, 1);
            ps0 += __shfl_xor_sync(0xffffffffu, ps0, 2);
            ps1 += __shfl_xor_sync(0xffffffffu, ps1, 1);
            ps1 += __shfl_xor_sync(0xffffffffu, ps1, 2);
            lrow0 = lrow0 * al0 + ps0;
            lrow1 = lrow1 * al1 + ps1;
#pragma unroll
            for (int j = 0; j < 8; j++) {
                oacc[j][0] *= al0; oacc[j][1] *= al0;
                oacc[j][2] *= al1; oacc[j][3] *= al1;
            }

            // ---- O += P_half V_half (3-pass hi/lo, P from S regs) ----
#pragma unroll
            for (int kt = 0; kt < 4; kt++) {
                const uint32_t ah0 = packbf(s[2 * kt][0],     s[2 * kt][1]);
                const uint32_t ah1 = packbf(s[2 * kt][2],     s[2 * kt][3]);
                const uint32_t ah2 = packbf(s[2 * kt + 1][0], s[2 * kt + 1][1]);
                const uint32_t ah3 = packbf(s[2 * kt + 1][2], s[2 * kt + 1][3]);
                const uint32_t al0_ = packlo(s[2 * kt][0],     s[2 * kt][1]);
                const uint32_t al1_ = packlo(s[2 * kt][2],     s[2 * kt][3]);
                const uint32_t al2_ = packlo(s[2 * kt + 1][0], s[2 * kt + 1][1]);
                const uint32_t al3_ = packlo(s[2 * kt + 1][2], s[2 * kt + 1][3]);
                const int gkt = half * 4 + kt;   // global 16-m-step in chunk
#pragma unroll
                for (int vg = 0; vg < 4; vg++) {
                    uint32_t vh4[4], vl4[4];
                    const int row = vg * 16 + frow;
                    const uint32_t off = row * 256 + ((((gkt << 1) + fchk) ^ (row & 15)) << 4);
                    ldm4(vh4[0], vh4[1], vh4[2], vh4[3], sVh + off);
                    ldm4(vl4[0], vl4[1], vl4[2], vl4[3], sVl + off);
#pragma unroll
                    for (int o = 0; o < 2; o++) {
                        float* a = oacc[vg * 2 + o];
                        mma_bf16(a[0], a[1], a[2], a[3], ah0, ah1, ah2, ah3,
                                 vh4[o], vh4[o + 2]);
                        mma_bf16(a[0], a[1], a[2], a[3], ah0, ah1, ah2, ah3,
                                 vl4[o], vl4[o + 2]);
                        mma_bf16(a[0], a[1], a[2], a[3], al0_, al1_, al2_, al3_,
                                 vh4[o], vh4[o + 2]);
                    }
                }
            }
        }
    }

    // ---- epilogue: normalize + write bf16 hi/lo at [b][n][h*64+dk] ----
    const float inv0 = 1.f / lrow0;
    const float inv1 = 1.f / lrow1;
    const int g = lid >> 2, t = lid & 3;
    const long r0 = n0 + wid * 16 + g;
    const long r1 = r0 + 8;
#pragma unroll
    for (int j = 0; j < 8; j++) {
        const int cc = h * 64 + j * 8 + t * 2;
        const float v00 = oacc[j][0] * inv0, v01 = oacc[j][1] * inv0;
        const float v10 = oacc[j][2] * inv1, v11 = oacc[j][3] * inv1;
        const long o0 = ((long)b * NN + r0) * DIM + cc;
        const long o1 = ((long)b * NN + r1) * DIM + cc;
        *(uint32_t*)(Oh + o0) = packbf(v00, v01);
        *(uint32_t*)(Oh + o1) = packbf(v10, v11);
        *(uint32_t*)(Ol + o0) = packlo(v00, v01);
        *(uint32_t*)(Ol + o1) = packlo(v10, v11);
    }
}

// ---------------------------------------------------------------------------
// Host launch
// ---------------------------------------------------------------------------
extern "C" void kernel_launch(void* const* d_in, const int* in_sizes, int n_in,
                              void* d_out, int out_size)
{
    const float* motion = (const float*)d_in[0];
    const float* Wq = (const float*)d_in[1];
    const float* bq = (const float*)d_in[2];
    const float* Wk = (const float*)d_in[3];
    const float* bk = (const float*)d_in[4];
    const float* Wv = (const float*)d_in[5];
    const float* bv = (const float*)d_in[6];
    const float* Wm = (const float*)d_in[7];
    const float* bm = (const float*)d_in[8];
    const float* Wp1 = (const float*)d_in[9];
    const float* bp1 = (const float*)d_in[10];
    const float* bng = (const float*)d_in[11];
    const float* bnb = (const float*)d_in[12];
    const float* bnm = (const float*)d_in[13];
    const float* bnv = (const float*)d_in[14];
    const float* Wp2 = (const float*)d_in[15];
    const float* bp2 = (const float*)d_in[16];
    float* out = (float*)d_out;

    float *MRG, *H1, *X0, *X1, *bqkv;
    cudaGetSymbolAddress((void**)&MRG, g_MRG);
    cudaGetSymbolAddress((void**)&H1,  g_H1);
    cudaGetSymbolAddress((void**)&X0,  g_X0);
    cudaGetSymbolAddress((void**)&X1,  g_X1);
    cudaGetSymbolAddress((void**)&bqkv, g_bqkv);

    __nv_bfloat16 *WqkvH, *WqkvL, *WmH, *WmL, *W1H, *W1L, *W2H, *W2L;
    __nv_bfloat16 *XTh, *XTl, *MTh, *MTl, *HTh, *HTl;
    __nv_bfloat16 *QKVh, *QKVl, *OTh, *OTl;
    cudaGetSymbolAddress((void**)&WqkvH, g_WqkvH); cudaGetSymbolAddress((void**)&WqkvL, g_WqkvL);
    cudaGetSymbolAddress((void**)&WmH, g_WmH); cudaGetSymbolAddress((void**)&WmL, g_WmL);
    cudaGetSymbolAddress((void**)&W1H, g_W1H); cudaGetSymbolAddress((void**)&W1L, g_W1L);
    cudaGetSymbolAddress((void**)&W2H, g_W2H); cudaGetSymbolAddress((void**)&W2L, g_W2L);
    cudaGetSymbolAddress((void**)&XTh, g_XTh); cudaGetSymbolAddress((void**)&XTl, g_XTl);
    cudaGetSymbolAddress((void**)&MTh, g_MTh); cudaGetSymbolAddress((void**)&MTl, g_MTl);
    cudaGetSymbolAddress((void**)&HTh, g_HTh); cudaGetSymbolAddress((void**)&HTl, g_HTl);
    cudaGetSymbolAddress((void**)&QKVh, g_QKVh); cudaGetSymbolAddress((void**)&QKVl, g_QKVl);
    cudaGetSymbolAddress((void**)&OTh, g_OTh); cudaGetSymbolAddress((void**)&OTl, g_OTl);

    cudaFuncSetAttribute(mma_gemm, cudaFuncAttributeMaxDynamicSharedMemorySize, MG_SMEM);
    cudaFuncSetAttribute(flash_k, cudaFuncAttributeMaxDynamicSharedMemorySize, FL_SMEM);

    // weight conversions (all layers)
    const int nDD   = LAYERS * DIM * DIM;
    const int n3DD  = LAYERS * 3 * DIM * DIM;
    const int n2D2  = LAYERS * TWOD * TWOD;
    const int nD2   = LAYERS * DIM * TWOD;
    cvt_qkv<<<n3DD / 1024, 256>>>(Wq, Wk, Wv, WqkvH, WqkvL);
    cvt_bias<<<(LAYERS * 3 * DIM) / 256, 256>>>(bq, bk, bv, bqkv);
    cvt_wm<<<nDD / 1024, 256>>>(Wm, WmH, WmL, nDD);   // column-permuted for head-blocked O
    cvt_w<<<n2D2 / 1024, 256>>>(Wp1, W1H, W1L, n2D2);
    cvt_w<<<nD2 / 1024, 256>>>(Wp2, W2H, W2L, nD2);

    const dim3 gT1(NN / 32, DIM / 32, BATCH);
    const dim3 gT2(NN / 32, TWOD / 32, BATCH);
    const dim3 blkT(32, 8);
    const dim3 gG1(32, DIM / 128);
    const dim3 gGqkv(32, (3 * DIM) / 128);
    const dim3 gG2(32, TWOD / 128);
    const dim3 gFl(NN / 128, BATCH * HEADS);
    const long cbs1 = (long)DIM * NN;
    const long cbs2 = (long)TWOD * NN;

    for (int l = 0; l < LAYERS; l++) {
        const float* xin = (l == 0) ? motion : ((l & 1) ? X1 : X0);
        float* xout = (l == 3) ? out : ((l & 1) ? X0 : X1);
        const long oDD  = (long)l * DIM * DIM;
        const long o3DD = (long)l * 3 * DIM * DIM;
        const long o2D2 = (long)l * TWOD * TWOD;
        const long oD2  = (long)l * DIM * TWOD;

        // x -> transposed bf16 hi/lo
        tcvt<<<gT1, blkT>>>(xin, XTh, XTl, DIM);

        // stacked QKV projection -> channel-major bf16 hi/lo (Q rows scaled 1/8)
        mma_gemm<<<gGqkv, 256, MG_SMEM>>>(WqkvH + o3DD, WqkvL + o3DD, DIM,
                                          XTh, XTl, DIM, 32, XTh, XTl, DIM, 32,
                                          bqkv + l * 3 * DIM,
                                          nullptr, nullptr, nullptr, nullptr,
                                          nullptr, nullptr, 0,
                                          QKVh, QKVl, 3 * DIM, DIM);

        // fused flash attention -> OTh/OTl (head-blocked bf16 hi/lo)
        flash_k<<<gFl, 256, FL_SMEM>>>(QKVh, QKVl, OTh, OTl);

        // merge projection (permuted weights, B = flash output directly)
        mma_gemm<<<gG1, 256, MG_SMEM>>>(WmH + oDD, WmL + oDD, DIM,
                                        OTh, OTl, DIM, 32, OTh, OTl, DIM, 32,
                                        bm + l * DIM, nullptr, nullptr, nullptr, nullptr,
                                        nullptr, MRG, cbs1,
                                        nullptr, nullptr, 0, 0);

        // p1: Wp1 @ concat(merged, x) + bias -> BN -> ReLU
        tcvt<<<gT1, blkT>>>(MRG, MTh, MTl, DIM);
        mma_gemm<<<gG2, 256, MG_SMEM>>>(W1H + o2D2, W1L + o2D2, TWOD,
                                        MTh, MTl, DIM, 32, XTh, XTl, DIM, 64,
                                        bp1 + l * TWOD,
                                        bng + l * TWOD, bnb + l * TWOD,
                                        bnm + l * TWOD, bnv + l * TWOD,
                                        nullptr, H1, cbs2,
                                        nullptr, nullptr, 0, 0);

        // p2: Wp2 @ h + bias + residual
        tcvt<<<gT2, blkT>>>(H1, HTh, HTl, TWOD);
        mma_gemm<<<gG1, 256, MG_SMEM>>>(W2H + oD2, W2L + oD2, TWOD,
                                        HTh, HTl, TWOD, 64, HTh, HTl, TWOD, 64,
                                        bp2 + l * DIM, nullptr, nullptr, nullptr, nullptr,
                                        xin, xout, cbs1,
                                        nullptr, nullptr, 0, 0);
    }
}